// round 2
// baseline (speedup 1.0000x reference)
#include <cuda_runtime.h>
#include <math.h>

#define H      128
#define EVT    4096
#define NN     20000
#define NE     320000
#define MAXN   100000
#define MSG    640

// ------------------- device scratch (static, allowed) -------------------
__device__ float    g_aggS[MAXN * MSG];     // 256 MB
__device__ float    g_aggD[MAXN * MSG];     // 256 MB
__device__ float    g_cntS[MAXN];
__device__ float    g_cntD[MAXN];
__device__ float    g_X   [2 * EVT * MSG];  // 8192 x 640
__device__ float    g_Hst [2 * EVT * H];    // 8192 x 128
__device__ float    g_GI  [2 * EVT * 384];
__device__ float    g_GH  [2 * EVT * 384];
__device__ float    g_newMem[2 * EVT * H];
__device__ int      g_tag [MAXN];           // 0 init; rewritten for touched ids each launch
__device__ float    g_attr[NE * 256];       // 327 MB
__device__ float    g_E   [NE * H];         // 164 MB
__device__ float    g_x   [NN * H];
__device__ float    g_q   [NN * H];
__device__ float    g_k   [NN * H];
__device__ float    g_v   [NN * H];
__device__ float    g_alpha[NE];
__device__ float    g_ex  [NE];
__device__ unsigned g_amaxKey[NN];
__device__ float    g_denom[NN];
__device__ float    g_wihT[640 * 384];
__device__ float    g_whhT[128 * 384];
__device__ float    g_weT [256 * 128];
__device__ float    g_wqT [128 * 128];
__device__ float    g_wkT [128 * 128];
__device__ float    g_wvT [128 * 128];
__device__ float    g_wsT [128 * 128];

// ------------------- helpers -------------------
__device__ __forceinline__ unsigned fkey(float f) {
    unsigned u = __float_as_uint(f);
    return (u & 0x80000000u) ? ~u : (u | 0x80000000u);
}
__device__ __forceinline__ float fdec(unsigned k) {
    return (k & 0x80000000u) ? __uint_as_float(k ^ 0x80000000u)
                             : __uint_as_float(~k);
}
__device__ __forceinline__ float get_time(const void* p) {
    int iv = *(const int*)p;                       // int32 / int64 (low word) path
    if (iv > -1000000 && iv < 1000000) return (float)iv;
    return *(const float*)p;                       // float32 fallback
}

// ------------------- transpose: dst(K x N) = src(N x K)^T -------------------
__global__ void k_transp(const float* __restrict__ src, float* __restrict__ dst,
                         int N, int K) {
    int o = blockIdx.x * blockDim.x + threadIdx.x;
    if (o >= N * K) return;
    int k = o / N, n = o % N;
    dst[o] = src[n * K + k];
}

// ------------------- zero touched agg entries -------------------
__global__ void k_zero(const int* __restrict__ sids, const int* __restrict__ dids) {
    int i = blockIdx.x;
    int sid = sids[i], did = dids[i];
    for (int t = threadIdx.x; t < MSG; t += blockDim.x) {
        g_aggS[sid * MSG + t] = 0.f;
        g_aggD[did * MSG + t] = 0.f;
    }
    if (threadIdx.x == 0) { g_cntS[sid] = 0.f; g_cntD[did] = 0.f; }
}

// ------------------- messages + scatter-sum -------------------
__global__ void __launch_bounds__(128) k_msg(
    const int* __restrict__ et, const int* __restrict__ sids,
    const float* __restrict__ smask, const int* __restrict__ dids,
    const float* __restrict__ dmask, const int* __restrict__ eids,
    const float* __restrict__ eemb, const float* __restrict__ emask,
    const float* __restrict__ ts, const float* __restrict__ last_update,
    const float* __restrict__ memory, const float* __restrict__ time_w,
    const float* __restrict__ time_b)
{
    int i = blockIdx.x, h = threadIdx.x;
    float em = emask[i], sm = smask[i], dm = dmask[i];
    int   etv = et[i];
    float tsv = ts[i];
    float el  = last_update[eids[i]];
    float rel = tsv - el * dm;
    float isn = (etv == 3 || etv == 4) ? 1.f : 0.f;
    float targ = tsv * isn + rel * dm;
    float cosv = cosf(targ * time_w[h] + time_b[h]) * em;   // ts_emb
    int sid = sids[i], did = dids[i];
    float sv = memory[sid * H + h] * sm;
    float dv = memory[did * H + h] * dm;
    float ev = eemb[i * H + h];
    float typ = (float)etv;

    float* aS = g_aggS + sid * MSG;
    atomicAdd(aS + 0 * H + h, typ  * em);
    atomicAdd(aS + 1 * H + h, sv   * em);
    atomicAdd(aS + 2 * H + h, dv   * em);
    atomicAdd(aS + 3 * H + h, cosv * em);
    atomicAdd(aS + 4 * H + h, ev   * em);
    float* aD = g_aggD + did * MSG;
    atomicAdd(aD + 0 * H + h, typ  * dm);
    atomicAdd(aD + 1 * H + h, dv   * dm);
    atomicAdd(aD + 2 * H + h, sv   * dm);
    atomicAdd(aD + 3 * H + h, cosv * dm);
    atomicAdd(aD + 4 * H + h, ev   * dm);
    if (h == 0) { atomicAdd(&g_cntS[sid], 1.f); atomicAdd(&g_cntD[did], 1.f); }
}

// ------------------- gather GRU inputs X (8192x640) and H (8192x128) -------------------
__global__ void __launch_bounds__(128) k_build_xh(
    const int* __restrict__ sids, const int* __restrict__ dids,
    const float* __restrict__ memory)
{
    int r = blockIdx.x;
    bool isS = r < EVT;
    int i = isS ? r : r - EVT;
    int id = isS ? sids[i] : dids[i];
    const float* agg = isS ? g_aggS : g_aggD;
    const float* cnt = isS ? g_cntS : g_cntD;
    float inv = 1.f / fmaxf(cnt[id], 1.f);
    for (int t = threadIdx.x; t < MSG; t += blockDim.x)
        g_X[r * MSG + t] = agg[id * MSG + t] * inv;
    for (int t = threadIdx.x; t < H; t += blockDim.x)
        g_Hst[r * H + t] = memory[id * H + t];
}

// ------------------- generic SGEMM: C(MxN) = A(MxK) @ WT(KxN) + bias -------------------
// 64x128 block tile, 4x8 per-thread tile, K chunked by 16.
__global__ void __launch_bounds__(256) k_gemm(
    const float* __restrict__ A, const float* __restrict__ WT,
    const float* __restrict__ bias, float* __restrict__ C,
    int M, int K, int N)
{
    __shared__ float sA[64 * 17];
    __shared__ float sW[16 * 128];
    int row0 = blockIdx.x * 64;
    int col0 = blockIdx.y * 128;
    int tid = threadIdx.x;
    int rg = tid >> 4, cg = tid & 15;
    float acc[4][8];
#pragma unroll
    for (int j = 0; j < 4; j++)
#pragma unroll
        for (int c = 0; c < 8; c++) acc[j][c] = 0.f;

    for (int kc = 0; kc < K; kc += 16) {
#pragma unroll
        for (int l = 0; l < 4; l++) {
            int idx = tid + l * 256;
            int row = idx >> 4, kk = idx & 15;
            int r = row0 + row;
            sA[row * 17 + kk] = (r < M) ? A[r * K + kc + kk] : 0.f;
        }
#pragma unroll
        for (int l = 0; l < 8; l++) {
            int idx = tid + l * 256;
            int kk = idx >> 7, n = idx & 127;
            sW[kk * 128 + n] = WT[(kc + kk) * N + col0 + n];
        }
        __syncthreads();
#pragma unroll
        for (int kk = 0; kk < 16; kk++) {
            float4 w0 = *(const float4*)&sW[kk * 128 + cg * 8];
            float4 w1 = *(const float4*)&sW[kk * 128 + cg * 8 + 4];
#pragma unroll
            for (int j = 0; j < 4; j++) {
                float a = sA[(rg * 4 + j) * 17 + kk];
                acc[j][0] += a * w0.x; acc[j][1] += a * w0.y;
                acc[j][2] += a * w0.z; acc[j][3] += a * w0.w;
                acc[j][4] += a * w1.x; acc[j][5] += a * w1.y;
                acc[j][6] += a * w1.z; acc[j][7] += a * w1.w;
            }
        }
        __syncthreads();
    }
    float4 b0 = make_float4(0.f, 0.f, 0.f, 0.f), b1 = b0;
    if (bias) {
        b0 = *(const float4*)&bias[col0 + cg * 8];
        b1 = *(const float4*)&bias[col0 + cg * 8 + 4];
    }
#pragma unroll
    for (int j = 0; j < 4; j++) {
        int r = row0 + rg * 4 + j;
        if (r < M) {
            float4 o0 = make_float4(acc[j][0] + b0.x, acc[j][1] + b0.y,
                                    acc[j][2] + b0.z, acc[j][3] + b0.w);
            float4 o1 = make_float4(acc[j][4] + b1.x, acc[j][5] + b1.y,
                                    acc[j][6] + b1.z, acc[j][7] + b1.w);
            *(float4*)&C[r * N + col0 + cg * 8]     = o0;
            *(float4*)&C[r * N + col0 + cg * 8 + 4] = o1;
        }
    }
}

// ------------------- GRU activation -------------------
__global__ void k_gru_act() {
    int idx = blockIdx.x * blockDim.x + threadIdx.x;   // < 8192*128
    int r = idx >> 7, h = idx & 127;
    float ir = g_GI[r * 384 + h];
    float iz = g_GI[r * 384 + 128 + h];
    float in_ = g_GI[r * 384 + 256 + h];
    float hr = g_GH[r * 384 + h];
    float hz = g_GH[r * 384 + 128 + h];
    float hn = g_GH[r * 384 + 256 + h];
    float rr = 1.f / (1.f + expf(-(ir + hr)));
    float zz = 1.f / (1.f + expf(-(iz + hz)));
    float nn = tanhf(in_ + rr * hn);
    float h0 = g_Hst[idx];
    g_newMem[idx] = (1.f - zz) * nn + zz * h0;
}

// ------------------- override tags (src pass then dst pass; dst wins) -------------------
__global__ void k_tag(const int* __restrict__ ids, int sgn) {
    int t = blockIdx.x * blockDim.x + threadIdx.x;
    if (t < EVT) g_tag[ids[t]] = (sgn > 0) ? (t + 1) : -(t + 1);
}

// ------------------- edge_attr build (320000 x 256) -------------------
__global__ void __launch_bounds__(256) k_attr(
    const int* __restrict__ eids, const float* __restrict__ last_update,
    const float* __restrict__ edge_features, const float* __restrict__ time_w,
    const float* __restrict__ time_b, const void* __restrict__ timep)
{
    int j = blockIdx.x, t = threadIdx.x;
    int eid = eids[j];
    float relt = get_time(timep) - last_update[eid];
    float v;
    if (t < H) v = cosf(relt * time_w[t] + time_b[t]);
    else       v = edge_features[eid * H + (t - H)];
    g_attr[j * 256 + t] = v;
}

// ------------------- x = node_features[nid] + updated_memory[nid] -------------------
__global__ void k_x(const int* __restrict__ node_ids,
                    const float* __restrict__ node_features,
                    const float* __restrict__ memory)
{
    int idx = blockIdx.x * blockDim.x + threadIdx.x;   // < NN*H
    int r = idx >> 7, h = idx & 127;
    int gid = node_ids[r];
    int tg = g_tag[gid];
    float mv = (tg > 0) ? g_newMem[(tg - 1) * H + h]
             : (tg < 0) ? g_newMem[(EVT + (-tg - 1)) * H + h]
                        : memory[gid * H + h];
    g_x[idx] = node_features[gid * H + h] + mv;
}

// ------------------- softmax state init -------------------
__global__ void k_init_nd() {
    int i = blockIdx.x * blockDim.x + threadIdx.x;
    if (i < NN) { g_amaxKey[i] = 0u; g_denom[i] = 0.f; }
}

// ------------------- alpha per edge + segment max -------------------
__global__ void __launch_bounds__(256) k_alpha(const int* __restrict__ ei) {
    int warp = threadIdx.x >> 5, lane = threadIdx.x & 31;
    int j = blockIdx.x * 8 + warp;
    int s = ei[j], d = ei[NE + j];
    float4 qv = ((const float4*)(g_q + d * H))[lane];
    float4 kv = ((const float4*)(g_k + s * H))[lane];
    float4 e4 = ((const float4*)(g_E + j * H))[lane];
    float p = qv.x * (kv.x + e4.x) + qv.y * (kv.y + e4.y)
            + qv.z * (kv.z + e4.z) + qv.w * (kv.w + e4.w);
#pragma unroll
    for (int o = 16; o; o >>= 1) p += __shfl_xor_sync(0xffffffffu, p, o);
    if (lane == 0) {
        float a = p * 0.08838834764831845f;   // 1/sqrt(128)
        g_alpha[j] = a;
        atomicMax(&g_amaxKey[d], fkey(a));
    }
}

// ------------------- exp + segment denom -------------------
__global__ void k_denom(const int* __restrict__ ei) {
    int j = blockIdx.x * blockDim.x + threadIdx.x;   // < NE
    int d = ei[NE + j];
    float ex = expf(g_alpha[j] - fdec(g_amaxKey[d]));
    g_ex[j] = ex;
    atomicAdd(&g_denom[d], ex);
}

// ------------------- weighted aggregation into out -------------------
__global__ void __launch_bounds__(256) k_out(const int* __restrict__ ei,
                                             float* __restrict__ out) {
    int warp = threadIdx.x >> 5, lane = threadIdx.x & 31;
    int j = blockIdx.x * 8 + warp;
    int s = ei[j], d = ei[NE + j];
    float p = g_ex[j] / fmaxf(g_denom[d], 1e-16f);
    float4 vv = ((const float4*)(g_v + s * H))[lane];
    float4 e4 = ((const float4*)(g_E + j * H))[lane];
    float* op = out + d * H + lane * 4;
    atomicAdd(op + 0, p * (vv.x + e4.x));
    atomicAdd(op + 1, p * (vv.y + e4.y));
    atomicAdd(op + 2, p * (vv.z + e4.z));
    atomicAdd(op + 3, p * (vv.w + e4.w));
}

// ------------------- host -------------------
static float* sym(const void* s) {
    void* p = nullptr;
    cudaGetSymbolAddress(&p, s);
    return (float*)p;
}

extern "C" void kernel_launch(void* const* d_in, const int* in_sizes, int n_in,
                              void* d_out, int out_size)
{
    const int*   event_type_ids = (const int*)  d_in[0];
    const int*   src_ids        = (const int*)  d_in[1];
    const float* src_mask       = (const float*)d_in[2];
    const int*   dst_ids        = (const int*)  d_in[3];
    const float* dst_mask       = (const float*)d_in[4];
    const int*   event_edge_ids = (const int*)  d_in[5];
    const float* event_emb      = (const float*)d_in[6];
    const float* event_mask     = (const float*)d_in[7];
    const float* event_ts       = (const float*)d_in[8];
    const int*   node_ids       = (const int*)  d_in[9];
    const int*   edge_ids       = (const int*)  d_in[10];
    const int*   edge_index     = (const int*)  d_in[11];
    const void*  timep          =               d_in[12];
    const float* memory         = (const float*)d_in[13];
    const float* last_update    = (const float*)d_in[14];
    const float* node_features  = (const float*)d_in[15];
    const float* edge_features  = (const float*)d_in[16];
    const float* time_w         = (const float*)d_in[17];
    const float* time_b         = (const float*)d_in[18];
    const float* gru_w_ih       = (const float*)d_in[19];
    const float* gru_w_hh       = (const float*)d_in[20];
    const float* gru_b_ih       = (const float*)d_in[21];
    const float* gru_b_hh       = (const float*)d_in[22];
    const float* wq             = (const float*)d_in[23];
    const float* bq             = (const float*)d_in[24];
    const float* wk             = (const float*)d_in[25];
    const float* bk             = (const float*)d_in[26];
    const float* wv             = (const float*)d_in[27];
    const float* bv             = (const float*)d_in[28];
    const float* we             = (const float*)d_in[29];
    const float* wskip          = (const float*)d_in[30];
    const float* bskip          = (const float*)d_in[31];
    float* out = (float*)d_out;

    float* pX    = sym(g_X);    float* pH    = sym(g_Hst);
    float* pGI   = sym(g_GI);   float* pGH   = sym(g_GH);
    float* pAttr = sym(g_attr); float* pE    = sym(g_E);
    float* px    = sym(g_x);    float* pq    = sym(g_q);
    float* pk    = sym(g_k);    float* pv    = sym(g_v);
    float* pwih  = sym(g_wihT); float* pwhh  = sym(g_whhT);
    float* pwe   = sym(g_weT);  float* pwq   = sym(g_wqT);
    float* pwk   = sym(g_wkT);  float* pwv   = sym(g_wvT);
    float* pws   = sym(g_wsT);

    // weight transposes
    k_transp<<<(384 * 640 + 255) / 256, 256>>>(gru_w_ih, pwih, 384, 640);
    k_transp<<<(384 * 128 + 255) / 256, 256>>>(gru_w_hh, pwhh, 384, 128);
    k_transp<<<(128 * 256 + 255) / 256, 256>>>(we,       pwe,  128, 256);
    k_transp<<<64, 256>>>(wq,    pwq, 128, 128);
    k_transp<<<64, 256>>>(wk,    pwk, 128, 128);
    k_transp<<<64, 256>>>(wv,    pwv, 128, 128);
    k_transp<<<64, 256>>>(wskip, pws, 128, 128);

    // message + aggregation
    k_zero<<<EVT, 256>>>(src_ids, dst_ids);
    k_msg<<<EVT, 128>>>(event_type_ids, src_ids, src_mask, dst_ids, dst_mask,
                        event_edge_ids, event_emb, event_mask, event_ts,
                        last_update, memory, time_w, time_b);
    k_build_xh<<<2 * EVT, 128>>>(src_ids, dst_ids, memory);

    // GRU
    k_gemm<<<dim3(128, 3), 256>>>(pX, pwih, gru_b_ih, pGI, 2 * EVT, 640, 384);
    k_gemm<<<dim3(128, 3), 256>>>(pH, pwhh, gru_b_hh, pGH, 2 * EVT, 128, 384);
    k_gru_act<<<(2 * EVT * H) / 256, 256>>>();
    k_tag<<<16, 256>>>(src_ids, 1);
    k_tag<<<16, 256>>>(dst_ids, -1);   // dst overrides src

    // edge attr + E-GEMM
    k_attr<<<NE, 256>>>(edge_ids, last_update, edge_features, time_w, time_b, timep);
    k_gemm<<<dim3((NE + 63) / 64, 1), 256>>>(pAttr, pwe, nullptr, pE, NE, 256, 128);

    // node features + q/k/v/skip
    k_x<<<(NN * H) / 256, 256>>>(node_ids, node_features, memory);
    k_gemm<<<dim3((NN + 63) / 64, 1), 256>>>(px, pwq, bq,    pq,  NN, 128, 128);
    k_gemm<<<dim3((NN + 63) / 64, 1), 256>>>(px, pwk, bk,    pk,  NN, 128, 128);
    k_gemm<<<dim3((NN + 63) / 64, 1), 256>>>(px, pwv, bv,    pv,  NN, 128, 128);
    k_gemm<<<dim3((NN + 63) / 64, 1), 256>>>(px, pws, bskip, out, NN, 128, 128); // out init = skip

    // attention softmax + aggregation
    k_init_nd<<<(NN + 255) / 256, 256>>>();
    k_alpha<<<NE / 8, 256>>>(edge_index);
    k_denom<<<NE / 256, 256>>>(edge_index);
    k_out<<<NE / 8, 256>>>(edge_index, out);
}

// round 5
// speedup vs baseline: 1.5586x; 1.5586x over previous
#include <cuda_runtime.h>
#include <math.h>

#define H      128
#define EVT    4096
#define NN     20000
#define NE     320000
#define MAXN   100000
#define MAXE   300000
#define MSG    640

// ------------------- device scratch (static, allowed) -------------------
__device__ float    g_aggS[MAXN * MSG];
__device__ float    g_aggD[MAXN * MSG];
__device__ float    g_cntS[MAXN];
__device__ float    g_cntD[MAXN];
__device__ float    g_X   [2 * EVT * MSG];
__device__ float    g_Hst [2 * EVT * H];
__device__ float    g_GI  [2 * EVT * 384];
__device__ float    g_GH  [2 * EVT * 384];
__device__ float    g_newMem[2 * EVT * H];
__device__ int      g_tag [MAXN];
// unique-edge machinery
__device__ int      g_flag[MAXE];      // 0-init; cleared at end of each launch
__device__ int      g_list[MAXE];
__device__ int      g_slot[MAXE];
__device__ int      g_ucount;          // 0-init; reset at end of each launch
__device__ int      g_eslot[NE];
__device__ float    g_AU  [MAXE * 256];   // compact edge_attr (unique eids)
__device__ float    g_Ec  [MAXE * H];     // compact E = attr @ we.T
__device__ float    g_x   [NN * H];
__device__ float    g_q   [NN * H];
__device__ float    g_k   [NN * H];
__device__ float    g_v   [NN * H];
__device__ float    g_alpha[NE];
__device__ float    g_ex  [NE];
__device__ unsigned g_amaxKey[NN];
__device__ float    g_denom[NN];
__device__ float    g_wihT[640 * 384];
__device__ float    g_whhT[128 * 384];
__device__ float    g_weT [256 * 128];
__device__ float    g_wqT [128 * 128];
__device__ float    g_wkT [128 * 128];
__device__ float    g_wvT [128 * 128];
__device__ float    g_wsT [128 * 128];

// ------------------- helpers -------------------
__device__ __forceinline__ unsigned fkey(float f) {
    unsigned u = __float_as_uint(f);
    return (u & 0x80000000u) ? ~u : (u | 0x80000000u);
}
__device__ __forceinline__ float fdec(unsigned k) {
    return (k & 0x80000000u) ? __uint_as_float(k ^ 0x80000000u)
                             : __uint_as_float(~k);
}
__device__ __forceinline__ float get_time(const void* p) {
    int iv = *(const int*)p;
    if (iv > -1000000 && iv < 1000000) return (float)iv;
    return *(const float*)p;
}
__device__ __forceinline__ unsigned long long ffma2(
    unsigned long long a, unsigned long long b, unsigned long long c) {
    asm("fma.rn.f32x2 %0, %1, %2, %3;" : "=l"(c) : "l"(a), "l"(b), "l"(c));
    return c;
}
__device__ __forceinline__ unsigned long long splat2(float x) {
    unsigned long long r;
    asm("mov.b64 %0, {%1, %1};" : "=l"(r) : "r"(__float_as_uint(x)));
    return r;
}

// ------------------- transpose: dst(K x N) = src(N x K)^T -------------------
__global__ void k_transp(const float* __restrict__ src, float* __restrict__ dst,
                         int N, int K) {
    int o = blockIdx.x * blockDim.x + threadIdx.x;
    if (o >= N * K) return;
    int k = o / N, n = o % N;
    dst[o] = src[n * K + k];
}

// ------------------- zero touched agg entries -------------------
__global__ void k_zero(const int* __restrict__ sids, const int* __restrict__ dids) {
    int i = blockIdx.x;
    int sid = sids[i], did = dids[i];
    for (int t = threadIdx.x; t < MSG; t += blockDim.x) {
        g_aggS[sid * MSG + t] = 0.f;
        g_aggD[did * MSG + t] = 0.f;
    }
    if (threadIdx.x == 0) { g_cntS[sid] = 0.f; g_cntD[did] = 0.f; }
}

// ------------------- messages + scatter-sum -------------------
__global__ void __launch_bounds__(128) k_msg(
    const int* __restrict__ et, const int* __restrict__ sids,
    const float* __restrict__ smask, const int* __restrict__ dids,
    const float* __restrict__ dmask, const int* __restrict__ eids,
    const float* __restrict__ eemb, const float* __restrict__ emask,
    const float* __restrict__ ts, const float* __restrict__ last_update,
    const float* __restrict__ memory, const float* __restrict__ time_w,
    const float* __restrict__ time_b)
{
    int i = blockIdx.x, h = threadIdx.x;
    float em = emask[i], sm = smask[i], dm = dmask[i];
    int   etv = et[i];
    float tsv = ts[i];
    float el  = last_update[eids[i]];
    float rel = tsv - el * dm;
    float isn = (etv == 3 || etv == 4) ? 1.f : 0.f;
    float targ = tsv * isn + rel * dm;
    float cosv = cosf(targ * time_w[h] + time_b[h]) * em;
    int sid = sids[i], did = dids[i];
    float sv = memory[sid * H + h] * sm;
    float dv = memory[did * H + h] * dm;
    float ev = eemb[i * H + h];
    float typ = (float)etv;

    float* aS = g_aggS + sid * MSG;
    atomicAdd(aS + 0 * H + h, typ  * em);
    atomicAdd(aS + 1 * H + h, sv   * em);
    atomicAdd(aS + 2 * H + h, dv   * em);
    atomicAdd(aS + 3 * H + h, cosv * em);
    atomicAdd(aS + 4 * H + h, ev   * em);
    float* aD = g_aggD + did * MSG;
    atomicAdd(aD + 0 * H + h, typ  * dm);
    atomicAdd(aD + 1 * H + h, dv   * dm);
    atomicAdd(aD + 2 * H + h, sv   * dm);
    atomicAdd(aD + 3 * H + h, cosv * dm);
    atomicAdd(aD + 4 * H + h, ev   * dm);
    if (h == 0) { atomicAdd(&g_cntS[sid], 1.f); atomicAdd(&g_cntD[did], 1.f); }
}

// ------------------- gather GRU inputs -------------------
__global__ void __launch_bounds__(128) k_build_xh(
    const int* __restrict__ sids, const int* __restrict__ dids,
    const float* __restrict__ memory)
{
    int r = blockIdx.x;
    bool isS = r < EVT;
    int i = isS ? r : r - EVT;
    int id = isS ? sids[i] : dids[i];
    const float* agg = isS ? g_aggS : g_aggD;
    const float* cnt = isS ? g_cntS : g_cntD;
    float inv = 1.f / fmaxf(cnt[id], 1.f);
    for (int t = threadIdx.x; t < MSG; t += blockDim.x)
        g_X[r * MSG + t] = agg[id * MSG + t] * inv;
    for (int t = threadIdx.x; t < H; t += blockDim.x)
        g_Hst[r * H + t] = memory[id * H + t];
}

// ------------------- SGEMM (f32x2): C(MxN)=A(MxK)@WT(KxN)+bias -------------------
// 128x128 block tile, 8x8 per-thread (row-paired f32x2 accumulators), BK=16.
__global__ void __launch_bounds__(256) k_gemm2(
    const float* __restrict__ A, const float* __restrict__ WT,
    const float* __restrict__ bias, float* __restrict__ C,
    int M, int K, int N, const int* __restrict__ Mdyn)
{
    if (Mdyn) M = *Mdyn;
    int row0 = blockIdx.x * 128;
    if (row0 >= M) return;
    int col0 = blockIdx.y * 128;
    __shared__ float sA[16 * 132];   // [kk][row], padded
    __shared__ float sW[16 * 128];   // [kk][col]
    int tid = threadIdx.x;
    int rg = tid >> 4, cg = tid & 15;

    unsigned long long acc[4][8];
#pragma unroll
    for (int pr = 0; pr < 4; pr++)
#pragma unroll
        for (int c = 0; c < 8; c++) acc[pr][c] = 0ull;

    for (int kc = 0; kc < K; kc += 16) {
#pragma unroll
        for (int l = 0; l < 2; l++) {
            int idx = tid + l * 256;            // 0..511
            int row = idx >> 2, seg = idx & 3;
            float4 v = make_float4(0.f, 0.f, 0.f, 0.f);
            int r = row0 + row;
            if (r < M) v = *(const float4*)&A[(long long)r * K + kc + seg * 4];
            sA[(seg * 4 + 0) * 132 + row] = v.x;
            sA[(seg * 4 + 1) * 132 + row] = v.y;
            sA[(seg * 4 + 2) * 132 + row] = v.z;
            sA[(seg * 4 + 3) * 132 + row] = v.w;
        }
#pragma unroll
        for (int l = 0; l < 2; l++) {
            int idx = tid + l * 256;            // 0..511
            int kk = idx >> 5, ns = idx & 31;
            *(float4*)&sW[kk * 128 + ns * 4] =
                *(const float4*)&WT[(long long)(kc + kk) * N + col0 + ns * 4];
        }
        __syncthreads();
#pragma unroll
        for (int kk = 0; kk < 16; kk++) {
            ulonglong2 a01 = *(const ulonglong2*)&sA[kk * 132 + rg * 8];
            ulonglong2 a23 = *(const ulonglong2*)&sA[kk * 132 + rg * 8 + 4];
            float4 wA = *(const float4*)&sW[kk * 128 + cg * 8];
            float4 wB = *(const float4*)&sW[kk * 128 + cg * 8 + 4];
            unsigned long long w[8] = {
                splat2(wA.x), splat2(wA.y), splat2(wA.z), splat2(wA.w),
                splat2(wB.x), splat2(wB.y), splat2(wB.z), splat2(wB.w)};
            unsigned long long ap[4] = {a01.x, a01.y, a23.x, a23.y};
#pragma unroll
            for (int pr = 0; pr < 4; pr++)
#pragma unroll
                for (int c = 0; c < 8; c++)
                    acc[pr][c] = ffma2(ap[pr], w[c], acc[pr][c]);
        }
        __syncthreads();
    }

    float b[8] = {0.f, 0.f, 0.f, 0.f, 0.f, 0.f, 0.f, 0.f};
    if (bias) {
        float4 b0 = *(const float4*)&bias[col0 + cg * 8];
        float4 b1 = *(const float4*)&bias[col0 + cg * 8 + 4];
        b[0] = b0.x; b[1] = b0.y; b[2] = b0.z; b[3] = b0.w;
        b[4] = b1.x; b[5] = b1.y; b[6] = b1.z; b[7] = b1.w;
    }
#pragma unroll
    for (int pr = 0; pr < 4; pr++) {
        int rlo = row0 + rg * 8 + pr * 2;
        float lo[8], hi[8];
#pragma unroll
        for (int c = 0; c < 8; c++) {
            lo[c] = __uint_as_float((unsigned)(acc[pr][c] & 0xffffffffull)) + b[c];
            hi[c] = __uint_as_float((unsigned)(acc[pr][c] >> 32)) + b[c];
        }
        if (rlo < M) {
            *(float4*)&C[(long long)rlo * N + col0 + cg * 8]     = make_float4(lo[0], lo[1], lo[2], lo[3]);
            *(float4*)&C[(long long)rlo * N + col0 + cg * 8 + 4] = make_float4(lo[4], lo[5], lo[6], lo[7]);
        }
        if (rlo + 1 < M) {
            *(float4*)&C[(long long)(rlo + 1) * N + col0 + cg * 8]     = make_float4(hi[0], hi[1], hi[2], hi[3]);
            *(float4*)&C[(long long)(rlo + 1) * N + col0 + cg * 8 + 4] = make_float4(hi[4], hi[5], hi[6], hi[7]);
        }
    }
}

// ------------------- GRU activation -------------------
__global__ void k_gru_act() {
    int idx = blockIdx.x * blockDim.x + threadIdx.x;
    int r = idx >> 7, h = idx & 127;
    float ir = g_GI[r * 384 + h];
    float iz = g_GI[r * 384 + 128 + h];
    float in_ = g_GI[r * 384 + 256 + h];
    float hr = g_GH[r * 384 + h];
    float hz = g_GH[r * 384 + 128 + h];
    float hn = g_GH[r * 384 + 256 + h];
    float rr = 1.f / (1.f + expf(-(ir + hr)));
    float zz = 1.f / (1.f + expf(-(iz + hz)));
    float nn = tanhf(in_ + rr * hn);
    float h0 = g_Hst[idx];
    g_newMem[idx] = (1.f - zz) * nn + zz * h0;
}

// ------------------- override tags -------------------
__global__ void k_tag(const int* __restrict__ ids, int sgn) {
    int t = blockIdx.x * blockDim.x + threadIdx.x;
    if (t < EVT) g_tag[ids[t]] = (sgn > 0) ? (t + 1) : -(t + 1);
}

// ------------------- unique-eid flagging -------------------
__global__ void k_flag(const int* __restrict__ eids) {
    int j = blockIdx.x * blockDim.x + threadIdx.x;
    if (j >= NE) return;
    int e = eids[j];
    if (atomicExch(&g_flag[e], 1) == 0) {
        int u = atomicAdd(&g_ucount, 1);
        g_list[u] = e;
        g_slot[e] = u;
    }
}
__global__ void k_eslot(const int* __restrict__ eids) {
    int j = blockIdx.x * blockDim.x + threadIdx.x;
    if (j < NE) g_eslot[j] = g_slot[eids[j]];
}
__global__ void k_unflag(const int* __restrict__ eids) {
    int j = blockIdx.x * blockDim.x + threadIdx.x;
    if (j < NE) g_flag[eids[j]] = 0;
    if (j == 0) g_ucount = 0;
}

// ------------------- compact edge_attr build (unique eids) -------------------
__global__ void __launch_bounds__(256) k_attr_u(
    const float* __restrict__ last_update, const float* __restrict__ EF,
    const float* __restrict__ tw, const float* __restrict__ tb,
    const void* __restrict__ timep)
{
    int u = blockIdx.x;
    if (u >= g_ucount) return;
    int e = g_list[u];
    int t = threadIdx.x;
    float relt = get_time(timep) - last_update[e];
    float v;
    if (t < H) v = __cosf(relt * tw[t] + tb[t]);
    else       v = EF[e * H + (t - H)];
    g_AU[u * 256 + t] = v;
}

// ------------------- x = node_features[nid] + updated_memory[nid] -------------------
__global__ void k_x(const int* __restrict__ node_ids,
                    const float* __restrict__ node_features,
                    const float* __restrict__ memory)
{
    int idx = blockIdx.x * blockDim.x + threadIdx.x;
    int r = idx >> 7, h = idx & 127;
    int gid = node_ids[r];
    int tg = g_tag[gid];
    float mv = (tg > 0) ? g_newMem[(tg - 1) * H + h]
             : (tg < 0) ? g_newMem[(EVT + (-tg - 1)) * H + h]
                        : memory[gid * H + h];
    g_x[idx] = node_features[gid * H + h] + mv;
}

// ------------------- softmax state init -------------------
__global__ void k_init_nd() {
    int i = blockIdx.x * blockDim.x + threadIdx.x;
    if (i < NN) { g_amaxKey[i] = 0u; g_denom[i] = 0.f; }
}

// ------------------- alpha per edge + segment max -------------------
__global__ void __launch_bounds__(256) k_alpha(const int* __restrict__ ei) {
    int warp = threadIdx.x >> 5, lane = threadIdx.x & 31;
    int j = blockIdx.x * 8 + warp;
    int s = ei[j], d = ei[NE + j];
    int u = g_eslot[j];
    float4 qv = ((const float4*)(g_q + d * H))[lane];
    float4 kv = ((const float4*)(g_k + s * H))[lane];
    float4 e4 = ((const float4*)(g_Ec + (size_t)u * H))[lane];
    float p = qv.x * (kv.x + e4.x) + qv.y * (kv.y + e4.y)
            + qv.z * (kv.z + e4.z) + qv.w * (kv.w + e4.w);
#pragma unroll
    for (int o = 16; o; o >>= 1) p += __shfl_xor_sync(0xffffffffu, p, o);
    if (lane == 0) {
        float a = p * 0.08838834764831845f;
        g_alpha[j] = a;
        atomicMax(&g_amaxKey[d], fkey(a));
    }
}

// ------------------- exp + segment denom -------------------
__global__ void k_denom(const int* __restrict__ ei) {
    int j = blockIdx.x * blockDim.x + threadIdx.x;
    int d = ei[NE + j];
    float ex = expf(g_alpha[j] - fdec(g_amaxKey[d]));
    g_ex[j] = ex;
    atomicAdd(&g_denom[d], ex);
}

// ------------------- weighted aggregation into out -------------------
__global__ void __launch_bounds__(256) k_out(const int* __restrict__ ei,
                                             float* __restrict__ out) {
    int warp = threadIdx.x >> 5, lane = threadIdx.x & 31;
    int j = blockIdx.x * 8 + warp;
    int s = ei[j], d = ei[NE + j];
    int u = g_eslot[j];
    float p = g_ex[j] / fmaxf(g_denom[d], 1e-16f);
    float4 vv = ((const float4*)(g_v + s * H))[lane];
    float4 e4 = ((const float4*)(g_Ec + (size_t)u * H))[lane];
    float* op = out + d * H + lane * 4;
    atomicAdd(op + 0, p * (vv.x + e4.x));
    atomicAdd(op + 1, p * (vv.y + e4.y));
    atomicAdd(op + 2, p * (vv.z + e4.z));
    atomicAdd(op + 3, p * (vv.w + e4.w));
}

// ------------------- host -------------------
static float* symf(const void* s) {
    void* p = nullptr;
    cudaGetSymbolAddress(&p, s);
    return (float*)p;
}

extern "C" void kernel_launch(void* const* d_in, const int* in_sizes, int n_in,
                              void* d_out, int out_size)
{
    const int*   event_type_ids = (const int*)  d_in[0];
    const int*   src_ids        = (const int*)  d_in[1];
    const float* src_mask       = (const float*)d_in[2];
    const int*   dst_ids        = (const int*)  d_in[3];
    const float* dst_mask       = (const float*)d_in[4];
    const int*   event_edge_ids = (const int*)  d_in[5];
    const float* event_emb      = (const float*)d_in[6];
    const float* event_mask     = (const float*)d_in[7];
    const float* event_ts       = (const float*)d_in[8];
    const int*   node_ids       = (const int*)  d_in[9];
    const int*   edge_ids       = (const int*)  d_in[10];
    const int*   edge_index     = (const int*)  d_in[11];
    const void*  timep          =               d_in[12];
    const float* memory         = (const float*)d_in[13];
    const float* last_update    = (const float*)d_in[14];
    const float* node_features  = (const float*)d_in[15];
    const float* edge_features  = (const float*)d_in[16];
    const float* time_w         = (const float*)d_in[17];
    const float* time_b         = (const float*)d_in[18];
    const float* gru_w_ih       = (const float*)d_in[19];
    const float* gru_w_hh       = (const float*)d_in[20];
    const float* gru_b_ih       = (const float*)d_in[21];
    const float* gru_b_hh       = (const float*)d_in[22];
    const float* wq             = (const float*)d_in[23];
    const float* bq             = (const float*)d_in[24];
    const float* wk             = (const float*)d_in[25];
    const float* bk             = (const float*)d_in[26];
    const float* wv             = (const float*)d_in[27];
    const float* bv             = (const float*)d_in[28];
    const float* we             = (const float*)d_in[29];
    const float* wskip          = (const float*)d_in[30];
    const float* bskip          = (const float*)d_in[31];
    float* out = (float*)d_out;

    float* pX    = symf(g_X);    float* pH    = symf(g_Hst);
    float* pGI   = symf(g_GI);   float* pGH   = symf(g_GH);
    float* pAU   = symf(g_AU);   float* pEc   = symf(g_Ec);
    float* px    = symf(g_x);    float* pq    = symf(g_q);
    float* pk    = symf(g_k);    float* pv    = symf(g_v);
    float* pwih  = symf(g_wihT); float* pwhh  = symf(g_whhT);
    float* pwe   = symf(g_weT);  float* pwq   = symf(g_wqT);
    float* pwk   = symf(g_wkT);  float* pwv   = symf(g_wvT);
    float* pws   = symf(g_wsT);
    void*  pUcntV = nullptr;
    cudaGetSymbolAddress(&pUcntV, g_ucount);   // templated overload: scalar symbol OK
    const int* pUcnt = (const int*)pUcntV;

    // weight transposes
    k_transp<<<(384 * 640 + 255) / 256, 256>>>(gru_w_ih, pwih, 384, 640);
    k_transp<<<(384 * 128 + 255) / 256, 256>>>(gru_w_hh, pwhh, 384, 128);
    k_transp<<<(128 * 256 + 255) / 256, 256>>>(we,       pwe,  128, 256);
    k_transp<<<64, 256>>>(wq,    pwq, 128, 128);
    k_transp<<<64, 256>>>(wk,    pwk, 128, 128);
    k_transp<<<64, 256>>>(wv,    pwv, 128, 128);
    k_transp<<<64, 256>>>(wskip, pws, 128, 128);

    // unique-eid flagging
    k_flag<<<(NE + 255) / 256, 256>>>(edge_ids);
    k_eslot<<<(NE + 255) / 256, 256>>>(edge_ids);

    // message + aggregation
    k_zero<<<EVT, 256>>>(src_ids, dst_ids);
    k_msg<<<EVT, 128>>>(event_type_ids, src_ids, src_mask, dst_ids, dst_mask,
                        event_edge_ids, event_emb, event_mask, event_ts,
                        last_update, memory, time_w, time_b);
    k_build_xh<<<2 * EVT, 128>>>(src_ids, dst_ids, memory);

    // GRU (f32x2 GEMMs)
    k_gemm2<<<dim3(64, 3), 256>>>(pX, pwih, gru_b_ih, pGI, 2 * EVT, 640, 384, nullptr);
    k_gemm2<<<dim3(64, 3), 256>>>(pH, pwhh, gru_b_hh, pGH, 2 * EVT, 128, 384, nullptr);
    k_gru_act<<<(2 * EVT * H) / 256, 256>>>();
    k_tag<<<16, 256>>>(src_ids, 1);
    k_tag<<<16, 256>>>(dst_ids, -1);   // dst overrides src

    // compact edge attr + E-GEMM over unique eids
    k_attr_u<<<MAXE, 256>>>(last_update, edge_features, time_w, time_b, timep);
    k_gemm2<<<dim3((MAXE + 127) / 128, 1), 256>>>(pAU, pwe, nullptr, pEc,
                                                  MAXE, 256, 128, pUcnt);

    // node features + q/k/v/skip
    k_x<<<(NN * H) / 256, 256>>>(node_ids, node_features, memory);
    k_gemm2<<<dim3((NN + 127) / 128, 1), 256>>>(px, pwq, bq,    pq,  NN, 128, 128, nullptr);
    k_gemm2<<<dim3((NN + 127) / 128, 1), 256>>>(px, pwk, bk,    pk,  NN, 128, 128, nullptr);
    k_gemm2<<<dim3((NN + 127) / 128, 1), 256>>>(px, pwv, bv,    pv,  NN, 128, 128, nullptr);
    k_gemm2<<<dim3((NN + 127) / 128, 1), 256>>>(px, pws, bskip, out, NN, 128, 128, nullptr);

    // attention softmax + aggregation
    k_init_nd<<<(NN + 255) / 256, 256>>>();
    k_alpha<<<NE / 8, 256>>>(edge_index);
    k_denom<<<NE / 256, 256>>>(edge_index);
    k_out<<<NE / 8, 256>>>(edge_index, out);

    // reset flags/count for next replay (graph-idempotent)
    k_unflag<<<(NE + 255) / 256, 256>>>(edge_ids);
}

// round 6
// speedup vs baseline: 2.3094x; 1.4817x over previous
#include <cuda_runtime.h>
#include <math.h>

#define H      128
#define EVT    4096
#define NN     20000
#define NE     320000
#define MAXN   100000
#define MAXE   300000
#define MSG    640

// ------------------- device scratch (static, allowed) -------------------
__device__ float    g_aggS[MAXN * MSG];
__device__ float    g_aggD[MAXN * MSG];
__device__ float    g_cntS[MAXN];
__device__ float    g_cntD[MAXN];
__device__ float    g_X   [2 * EVT * MSG];
__device__ float    g_Hst [2 * EVT * H];
__device__ float    g_GI  [2 * EVT * 384];
__device__ float    g_GH  [2 * EVT * 384];
__device__ float    g_newMem[2 * EVT * H];
__device__ int      g_tag [MAXN];
// unique-edge machinery
__device__ int      g_flag[MAXE];
__device__ int      g_list[MAXE];
__device__ int      g_slot[MAXE];
__device__ int      g_ucount;
__device__ int      g_eslot[NE];
__device__ float    g_AU  [MAXE * 256];
__device__ float    g_Ec  [MAXE * H];
__device__ float    g_x   [NN * H];
__device__ float    g_q   [NN * H];
__device__ float    g_k   [NN * H];
__device__ float    g_v   [NN * H];
__device__ float    g_alpha[NE];
__device__ float    g_ex  [NE];
__device__ unsigned g_amaxKey[NN];
__device__ float    g_denom[NN];
__device__ float    g_wihT[640 * 384];
__device__ float    g_whhT[128 * 384];
__device__ float    g_weT [256 * 128];
__device__ float    g_wqT [128 * 128];
__device__ float    g_wkT [128 * 128];
__device__ float    g_wvT [128 * 128];
__device__ float    g_wsT [128 * 128];

// ------------------- helpers -------------------
__device__ __forceinline__ unsigned fkey(float f) {
    unsigned u = __float_as_uint(f);
    return (u & 0x80000000u) ? ~u : (u | 0x80000000u);
}
__device__ __forceinline__ float fdec(unsigned k) {
    return (k & 0x80000000u) ? __uint_as_float(k ^ 0x80000000u)
                             : __uint_as_float(~k);
}
__device__ __forceinline__ float get_time(const void* p) {
    int iv = *(const int*)p;
    if (iv > -1000000 && iv < 1000000) return (float)iv;
    return *(const float*)p;
}
__device__ __forceinline__ unsigned f2tf32(float f) {
    unsigned r;
    asm("cvt.rna.tf32.f32 %0, %1;" : "=r"(r) : "f"(f));
    return r;
}
__device__ __forceinline__ void mma_tf32(float* d, const unsigned* a, const unsigned* b) {
    asm("mma.sync.aligned.m16n8k8.row.col.f32.tf32.tf32.f32 "
        "{%0,%1,%2,%3}, {%4,%5,%6,%7}, {%8,%9}, {%0,%1,%2,%3};"
        : "+f"(d[0]), "+f"(d[1]), "+f"(d[2]), "+f"(d[3])
        : "r"(a[0]), "r"(a[1]), "r"(a[2]), "r"(a[3]), "r"(b[0]), "r"(b[1]));
}

// ------------------- transpose: dst(K x N) = src(N x K)^T -------------------
__global__ void k_transp(const float* __restrict__ src, float* __restrict__ dst,
                         int N, int K) {
    int o = blockIdx.x * blockDim.x + threadIdx.x;
    if (o >= N * K) return;
    int k = o / N, n = o % N;
    dst[o] = src[n * K + k];
}

// ------------------- zero touched agg entries -------------------
__global__ void k_zero(const int* __restrict__ sids, const int* __restrict__ dids) {
    int i = blockIdx.x;
    int sid = sids[i], did = dids[i];
    for (int t = threadIdx.x; t < MSG; t += blockDim.x) {
        g_aggS[sid * MSG + t] = 0.f;
        g_aggD[did * MSG + t] = 0.f;
    }
    if (threadIdx.x == 0) { g_cntS[sid] = 0.f; g_cntD[did] = 0.f; }
}

// ------------------- messages + scatter-sum -------------------
__global__ void __launch_bounds__(128) k_msg(
    const int* __restrict__ et, const int* __restrict__ sids,
    const float* __restrict__ smask, const int* __restrict__ dids,
    const float* __restrict__ dmask, const int* __restrict__ eids,
    const float* __restrict__ eemb, const float* __restrict__ emask,
    const float* __restrict__ ts, const float* __restrict__ last_update,
    const float* __restrict__ memory, const float* __restrict__ time_w,
    const float* __restrict__ time_b)
{
    int i = blockIdx.x, h = threadIdx.x;
    float em = emask[i], sm = smask[i], dm = dmask[i];
    int   etv = et[i];
    float tsv = ts[i];
    float el  = last_update[eids[i]];
    float rel = tsv - el * dm;
    float isn = (etv == 3 || etv == 4) ? 1.f : 0.f;
    float targ = tsv * isn + rel * dm;
    float cosv = cosf(targ * time_w[h] + time_b[h]) * em;
    int sid = sids[i], did = dids[i];
    float sv = memory[sid * H + h] * sm;
    float dv = memory[did * H + h] * dm;
    float ev = eemb[i * H + h];
    float typ = (float)etv;

    float* aS = g_aggS + sid * MSG;
    atomicAdd(aS + 0 * H + h, typ  * em);
    atomicAdd(aS + 1 * H + h, sv   * em);
    atomicAdd(aS + 2 * H + h, dv   * em);
    atomicAdd(aS + 3 * H + h, cosv * em);
    atomicAdd(aS + 4 * H + h, ev   * em);
    float* aD = g_aggD + did * MSG;
    atomicAdd(aD + 0 * H + h, typ  * dm);
    atomicAdd(aD + 1 * H + h, dv   * dm);
    atomicAdd(aD + 2 * H + h, sv   * dm);
    atomicAdd(aD + 3 * H + h, cosv * dm);
    atomicAdd(aD + 4 * H + h, ev   * dm);
    if (h == 0) { atomicAdd(&g_cntS[sid], 1.f); atomicAdd(&g_cntD[did], 1.f); }
}

// ------------------- gather GRU inputs -------------------
__global__ void __launch_bounds__(128) k_build_xh(
    const int* __restrict__ sids, const int* __restrict__ dids,
    const float* __restrict__ memory)
{
    int r = blockIdx.x;
    bool isS = r < EVT;
    int i = isS ? r : r - EVT;
    int id = isS ? sids[i] : dids[i];
    const float* agg = isS ? g_aggS : g_aggD;
    const float* cnt = isS ? g_cntS : g_cntD;
    float inv = 1.f / fmaxf(cnt[id], 1.f);
    for (int t = threadIdx.x; t < MSG; t += blockDim.x)
        g_X[r * MSG + t] = agg[id * MSG + t] * inv;
    for (int t = threadIdx.x; t < H; t += blockDim.x)
        g_Hst[r * H + t] = memory[id * H + t];
}

// ------------------- tf32 tensor-core GEMM: C(MxN)=A(MxK)@WT(KxN)+bias -------------------
// 128x128 block tile, BK=32, 8 warps (each 32x64), m16n8k8 tf32 MMA.
// sA pitch 36 / sW pitch 136 give conflict-free fragment loads.
__global__ void __launch_bounds__(256, 2) k_gemm_tc(
    const float* __restrict__ A, const float* __restrict__ WT,
    const float* __restrict__ bias, float* __restrict__ C,
    int M, int K, int N, const int* __restrict__ Mdyn)
{
    if (Mdyn) M = *Mdyn;
    int row0 = blockIdx.x * 128;
    if (row0 >= M) return;
    int col0 = blockIdx.y * 128;
    __shared__ unsigned sA[128 * 36];
    __shared__ unsigned sW[32 * 136];
    int tid = threadIdx.x, lane = tid & 31, wid = tid >> 5;
    int wm = wid & 3, wn = wid >> 2;       // warp tile: rows wm*32, cols wn*64
    int gid = lane >> 2, tig = lane & 3;

    float acc[2][8][4];
#pragma unroll
    for (int mt = 0; mt < 2; mt++)
#pragma unroll
        for (int nt = 0; nt < 8; nt++)
#pragma unroll
            for (int c = 0; c < 4; c++) acc[mt][nt][c] = 0.f;

    for (int kc = 0; kc < K; kc += 32) {
        // stage A chunk (128 x 32), tf32-rounded
#pragma unroll
        for (int l = 0; l < 4; l++) {
            int idx = tid + l * 256;               // 0..1023
            int row = idx >> 3, c4 = (idx & 7) * 4;
            float4 v = make_float4(0.f, 0.f, 0.f, 0.f);
            int r = row0 + row;
            if (r < M) v = *(const float4*)&A[(size_t)r * K + kc + c4];
            uint4 t;
            t.x = f2tf32(v.x); t.y = f2tf32(v.y);
            t.z = f2tf32(v.z); t.w = f2tf32(v.w);
            *(uint4*)&sA[row * 36 + c4] = t;
        }
        // stage W chunk (32 x 128), tf32-rounded
#pragma unroll
        for (int l = 0; l < 4; l++) {
            int idx = tid + l * 256;               // 0..1023
            int k = idx >> 5, n4 = (idx & 31) * 4;
            float4 v = *(const float4*)&WT[(size_t)(kc + k) * N + col0 + n4];
            uint4 t;
            t.x = f2tf32(v.x); t.y = f2tf32(v.y);
            t.z = f2tf32(v.z); t.w = f2tf32(v.w);
            *(uint4*)&sW[k * 136 + n4] = t;
        }
        __syncthreads();
#pragma unroll
        for (int k8 = 0; k8 < 32; k8 += 8) {
            unsigned a[2][4];
#pragma unroll
            for (int mt = 0; mt < 2; mt++) {
                int r = wm * 32 + mt * 16;
                a[mt][0] = sA[(r + gid    ) * 36 + k8 + tig    ];
                a[mt][1] = sA[(r + gid + 8) * 36 + k8 + tig    ];
                a[mt][2] = sA[(r + gid    ) * 36 + k8 + tig + 4];
                a[mt][3] = sA[(r + gid + 8) * 36 + k8 + tig + 4];
            }
#pragma unroll
            for (int nt = 0; nt < 8; nt++) {
                int n = wn * 64 + nt * 8 + gid;
                unsigned b[2];
                b[0] = sW[(k8 + tig    ) * 136 + n];
                b[1] = sW[(k8 + tig + 4) * 136 + n];
                mma_tf32(acc[0][nt], a[0], b);
                mma_tf32(acc[1][nt], a[1], b);
            }
        }
        __syncthreads();
    }

    // epilogue: c0,c1 -> (row, col), (row, col+1); c2,c3 -> row+8
#pragma unroll
    for (int mt = 0; mt < 2; mt++) {
#pragma unroll
        for (int nt = 0; nt < 8; nt++) {
            int col = col0 + wn * 64 + nt * 8 + tig * 2;
            float b0 = 0.f, b1 = 0.f;
            if (bias) { b0 = bias[col]; b1 = bias[col + 1]; }
            int r0 = row0 + wm * 32 + mt * 16 + gid;
            if (r0 < M) {
                float2 o = make_float2(acc[mt][nt][0] + b0, acc[mt][nt][1] + b1);
                *(float2*)&C[(size_t)r0 * N + col] = o;
            }
            if (r0 + 8 < M) {
                float2 o = make_float2(acc[mt][nt][2] + b0, acc[mt][nt][3] + b1);
                *(float2*)&C[(size_t)(r0 + 8) * N + col] = o;
            }
        }
    }
}

// ------------------- GRU activation -------------------
__global__ void k_gru_act() {
    int idx = blockIdx.x * blockDim.x + threadIdx.x;
    int r = idx >> 7, h = idx & 127;
    float ir = g_GI[r * 384 + h];
    float iz = g_GI[r * 384 + 128 + h];
    float in_ = g_GI[r * 384 + 256 + h];
    float hr = g_GH[r * 384 + h];
    float hz = g_GH[r * 384 + 128 + h];
    float hn = g_GH[r * 384 + 256 + h];
    float rr = 1.f / (1.f + expf(-(ir + hr)));
    float zz = 1.f / (1.f + expf(-(iz + hz)));
    float nn = tanhf(in_ + rr * hn);
    float h0 = g_Hst[idx];
    g_newMem[idx] = (1.f - zz) * nn + zz * h0;
}

// ------------------- override tags -------------------
__global__ void k_tag(const int* __restrict__ ids, int sgn) {
    int t = blockIdx.x * blockDim.x + threadIdx.x;
    if (t < EVT) g_tag[ids[t]] = (sgn > 0) ? (t + 1) : -(t + 1);
}

// ------------------- unique-eid flagging -------------------
__global__ void k_flag(const int* __restrict__ eids) {
    int j = blockIdx.x * blockDim.x + threadIdx.x;
    if (j >= NE) return;
    int e = eids[j];
    if (atomicExch(&g_flag[e], 1) == 0) {
        int u = atomicAdd(&g_ucount, 1);
        g_list[u] = e;
        g_slot[e] = u;
    }
}
__global__ void k_eslot(const int* __restrict__ eids) {
    int j = blockIdx.x * blockDim.x + threadIdx.x;
    if (j < NE) g_eslot[j] = g_slot[eids[j]];
}
__global__ void k_unflag(const int* __restrict__ eids) {
    int j = blockIdx.x * blockDim.x + threadIdx.x;
    if (j < NE) g_flag[eids[j]] = 0;
    if (j == 0) g_ucount = 0;
}

// ------------------- compact edge_attr build (unique eids) -------------------
__global__ void __launch_bounds__(256) k_attr_u(
    const float* __restrict__ last_update, const float* __restrict__ EF,
    const float* __restrict__ tw, const float* __restrict__ tb,
    const void* __restrict__ timep)
{
    int u = blockIdx.x;
    if (u >= g_ucount) return;
    int e = g_list[u];
    int t = threadIdx.x;
    float relt = get_time(timep) - last_update[e];
    float v;
    if (t < H) v = __cosf(relt * tw[t] + tb[t]);
    else       v = EF[e * H + (t - H)];
    g_AU[u * 256 + t] = v;
}

// ------------------- x = node_features[nid] + updated_memory[nid] -------------------
__global__ void k_x(const int* __restrict__ node_ids,
                    const float* __restrict__ node_features,
                    const float* __restrict__ memory)
{
    int idx = blockIdx.x * blockDim.x + threadIdx.x;
    int r = idx >> 7, h = idx & 127;
    int gid = node_ids[r];
    int tg = g_tag[gid];
    float mv = (tg > 0) ? g_newMem[(tg - 1) * H + h]
             : (tg < 0) ? g_newMem[(EVT + (-tg - 1)) * H + h]
                        : memory[gid * H + h];
    g_x[idx] = node_features[gid * H + h] + mv;
}

// ------------------- softmax state init -------------------
__global__ void k_init_nd() {
    int i = blockIdx.x * blockDim.x + threadIdx.x;
    if (i < NN) { g_amaxKey[i] = 0u; g_denom[i] = 0.f; }
}

// ------------------- alpha per edge + segment max -------------------
__global__ void __launch_bounds__(256) k_alpha(const int* __restrict__ ei) {
    int warp = threadIdx.x >> 5, lane = threadIdx.x & 31;
    int j = blockIdx.x * 8 + warp;
    int s = ei[j], d = ei[NE + j];
    int u = g_eslot[j];
    float4 qv = ((const float4*)(g_q + d * H))[lane];
    float4 kv = ((const float4*)(g_k + s * H))[lane];
    float4 e4 = ((const float4*)(g_Ec + (size_t)u * H))[lane];
    float p = qv.x * (kv.x + e4.x) + qv.y * (kv.y + e4.y)
            + qv.z * (kv.z + e4.z) + qv.w * (kv.w + e4.w);
#pragma unroll
    for (int o = 16; o; o >>= 1) p += __shfl_xor_sync(0xffffffffu, p, o);
    if (lane == 0) {
        float a = p * 0.08838834764831845f;
        g_alpha[j] = a;
        atomicMax(&g_amaxKey[d], fkey(a));
    }
}

// ------------------- exp + segment denom -------------------
__global__ void k_denom(const int* __restrict__ ei) {
    int j = blockIdx.x * blockDim.x + threadIdx.x;
    int d = ei[NE + j];
    float ex = expf(g_alpha[j] - fdec(g_amaxKey[d]));
    g_ex[j] = ex;
    atomicAdd(&g_denom[d], ex);
}

// ------------------- weighted aggregation into out -------------------
__global__ void __launch_bounds__(256) k_out(const int* __restrict__ ei,
                                             float* __restrict__ out) {
    int warp = threadIdx.x >> 5, lane = threadIdx.x & 31;
    int j = blockIdx.x * 8 + warp;
    int s = ei[j], d = ei[NE + j];
    int u = g_eslot[j];
    float p = g_ex[j] / fmaxf(g_denom[d], 1e-16f);
    float4 vv = ((const float4*)(g_v + s * H))[lane];
    float4 e4 = ((const float4*)(g_Ec + (size_t)u * H))[lane];
    float* op = out + d * H + lane * 4;
    atomicAdd(op + 0, p * (vv.x + e4.x));
    atomicAdd(op + 1, p * (vv.y + e4.y));
    atomicAdd(op + 2, p * (vv.z + e4.z));
    atomicAdd(op + 3, p * (vv.w + e4.w));
}

// ------------------- host -------------------
static float* symf(const void* s) {
    void* p = nullptr;
    cudaGetSymbolAddress(&p, s);
    return (float*)p;
}

extern "C" void kernel_launch(void* const* d_in, const int* in_sizes, int n_in,
                              void* d_out, int out_size)
{
    const int*   event_type_ids = (const int*)  d_in[0];
    const int*   src_ids        = (const int*)  d_in[1];
    const float* src_mask       = (const float*)d_in[2];
    const int*   dst_ids        = (const int*)  d_in[3];
    const float* dst_mask       = (const float*)d_in[4];
    const int*   event_edge_ids = (const int*)  d_in[5];
    const float* event_emb      = (const float*)d_in[6];
    const float* event_mask     = (const float*)d_in[7];
    const float* event_ts       = (const float*)d_in[8];
    const int*   node_ids       = (const int*)  d_in[9];
    const int*   edge_ids       = (const int*)  d_in[10];
    const int*   edge_index     = (const int*)  d_in[11];
    const void*  timep          =               d_in[12];
    const float* memory         = (const float*)d_in[13];
    const float* last_update    = (const float*)d_in[14];
    const float* node_features  = (const float*)d_in[15];
    const float* edge_features  = (const float*)d_in[16];
    const float* time_w         = (const float*)d_in[17];
    const float* time_b         = (const float*)d_in[18];
    const float* gru_w_ih       = (const float*)d_in[19];
    const float* gru_w_hh       = (const float*)d_in[20];
    const float* gru_b_ih       = (const float*)d_in[21];
    const float* gru_b_hh       = (const float*)d_in[22];
    const float* wq             = (const float*)d_in[23];
    const float* bq             = (const float*)d_in[24];
    const float* wk             = (const float*)d_in[25];
    const float* bk             = (const float*)d_in[26];
    const float* wv             = (const float*)d_in[27];
    const float* bv             = (const float*)d_in[28];
    const float* we             = (const float*)d_in[29];
    const float* wskip          = (const float*)d_in[30];
    const float* bskip          = (const float*)d_in[31];
    float* out = (float*)d_out;

    float* pX    = symf(g_X);    float* pH    = symf(g_Hst);
    float* pGI   = symf(g_GI);   float* pGH   = symf(g_GH);
    float* pAU   = symf(g_AU);   float* pEc   = symf(g_Ec);
    float* px    = symf(g_x);    float* pq    = symf(g_q);
    float* pk    = symf(g_k);    float* pv    = symf(g_v);
    float* pwih  = symf(g_wihT); float* pwhh  = symf(g_whhT);
    float* pwe   = symf(g_weT);  float* pwq   = symf(g_wqT);
    float* pwk   = symf(g_wkT);  float* pwv   = symf(g_wvT);
    float* pws   = symf(g_wsT);
    void*  pUcntV = nullptr;
    cudaGetSymbolAddress(&pUcntV, g_ucount);
    const int* pUcnt = (const int*)pUcntV;

    // weight transposes
    k_transp<<<(384 * 640 + 255) / 256, 256>>>(gru_w_ih, pwih, 384, 640);
    k_transp<<<(384 * 128 + 255) / 256, 256>>>(gru_w_hh, pwhh, 384, 128);
    k_transp<<<(128 * 256 + 255) / 256, 256>>>(we,       pwe,  128, 256);
    k_transp<<<64, 256>>>(wq,    pwq, 128, 128);
    k_transp<<<64, 256>>>(wk,    pwk, 128, 128);
    k_transp<<<64, 256>>>(wv,    pwv, 128, 128);
    k_transp<<<64, 256>>>(wskip, pws, 128, 128);

    // unique-eid flagging
    k_flag<<<(NE + 255) / 256, 256>>>(edge_ids);
    k_eslot<<<(NE + 255) / 256, 256>>>(edge_ids);

    // message + aggregation
    k_zero<<<EVT, 256>>>(src_ids, dst_ids);
    k_msg<<<EVT, 128>>>(event_type_ids, src_ids, src_mask, dst_ids, dst_mask,
                        event_edge_ids, event_emb, event_mask, event_ts,
                        last_update, memory, time_w, time_b);
    k_build_xh<<<2 * EVT, 128>>>(src_ids, dst_ids, memory);

    // GRU (tf32 tensor-core GEMMs)
    k_gemm_tc<<<dim3(64, 3), 256>>>(pX, pwih, gru_b_ih, pGI, 2 * EVT, 640, 384, nullptr);
    k_gemm_tc<<<dim3(64, 3), 256>>>(pH, pwhh, gru_b_hh, pGH, 2 * EVT, 128, 384, nullptr);
    k_gru_act<<<(2 * EVT * H) / 256, 256>>>();
    k_tag<<<16, 256>>>(src_ids, 1);
    k_tag<<<16, 256>>>(dst_ids, -1);   // dst overrides src

    // compact edge attr + E-GEMM over unique eids
    k_attr_u<<<MAXE, 256>>>(last_update, edge_features, time_w, time_b, timep);
    k_gemm_tc<<<dim3((MAXE + 127) / 128, 1), 256>>>(pAU, pwe, nullptr, pEc,
                                                    MAXE, 256, 128, pUcnt);

    // node features + q/k/v/skip
    k_x<<<(NN * H) / 256, 256>>>(node_ids, node_features, memory);
    k_gemm_tc<<<dim3((NN + 127) / 128, 1), 256>>>(px, pwq, bq,    pq,  NN, 128, 128, nullptr);
    k_gemm_tc<<<dim3((NN + 127) / 128, 1), 256>>>(px, pwk, bk,    pk,  NN, 128, 128, nullptr);
    k_gemm_tc<<<dim3((NN + 127) / 128, 1), 256>>>(px, pwv, bv,    pv,  NN, 128, 128, nullptr);
    k_gemm_tc<<<dim3((NN + 127) / 128, 1), 256>>>(px, pws, bskip, out, NN, 128, 128, nullptr);

    // attention softmax + aggregation
    k_init_nd<<<(NN + 255) / 256, 256>>>();
    k_alpha<<<NE / 8, 256>>>(edge_index);
    k_denom<<<NE / 256, 256>>>(edge_index);
    k_out<<<NE / 8, 256>>>(edge_index, out);

    // reset flags/count for next replay (graph-idempotent)
    k_unflag<<<(NE + 255) / 256, 256>>>(edge_ids);
}

// round 9
// speedup vs baseline: 3.5207x; 1.5245x over previous
#include <cuda_runtime.h>
#include <math.h>

#define H      128
#define EVT    4096
#define NN     20000
#define NE     320000
#define MAXN   100000
#define MAXE   300000
#define MSG    640

// ------------------- device scratch (static, allowed) -------------------
__device__ float    g_aggS[MAXN * MSG];
__device__ float    g_aggD[MAXN * MSG];
__device__ float    g_cntS[MAXN];
__device__ float    g_cntD[MAXN];
__device__ float    g_X   [2 * EVT * MSG];
__device__ float    g_Hst [2 * EVT * H];
__device__ float    g_GI  [2 * EVT * 384];
__device__ float    g_GH  [2 * EVT * 384];
__device__ float    g_newMem[2 * EVT * H];
__device__ int      g_tag [MAXN];
// unique-edge machinery
__device__ int      g_flag[MAXE];      // 0-init; cleared at end of each launch
__device__ int      g_list[MAXE];
__device__ int      g_slot[MAXE];
__device__ int      g_ucount;          // 0-init; reset at end of each launch
__device__ float    g_urelt[MAXE];
__device__ float    g_Ec  [MAXE * H];     // compact E = attr @ we.T
__device__ float    g_x   [NN * H];
__device__ float    g_qkvs[NN * 512];     // [q | k | v | skip]
// dst-sorted edge machinery
__device__ int      g_cnt [NN];
__device__ int      g_off [NN + 1];
__device__ int      g_cur [NN];
__device__ int      g_ss  [NE];           // src, sorted by dst
__device__ int      g_sd  [NE];           // dst, sorted
__device__ int      g_su  [NE];           // unique-eid slot, sorted
__device__ float    g_salpha[NE];
// weights
__device__ float    g_wihT[640 * 384];
__device__ float    g_whhT[128 * 384];
__device__ float    g_weT [256 * 128];
__device__ float    g_wcT [128 * 512];    // packed q|k|v|skip transposed
__device__ float    g_bc  [512];

// ------------------- helpers -------------------
__device__ __forceinline__ float get_time(const void* p) {
    int iv = *(const int*)p;
    if (iv > -1000000 && iv < 1000000) return (float)iv;
    return *(const float*)p;
}
__device__ __forceinline__ unsigned f2tf32(float f) {
    unsigned r;
    asm("cvt.rna.tf32.f32 %0, %1;" : "=r"(r) : "f"(f));
    return r;
}
__device__ __forceinline__ void mma_tf32(float* d, const unsigned* a, const unsigned* b) {
    asm("mma.sync.aligned.m16n8k8.row.col.f32.tf32.tf32.f32 "
        "{%0,%1,%2,%3}, {%4,%5,%6,%7}, {%8,%9}, {%0,%1,%2,%3};"
        : "+f"(d[0]), "+f"(d[1]), "+f"(d[2]), "+f"(d[3])
        : "r"(a[0]), "r"(a[1]), "r"(a[2]), "r"(a[3]), "r"(b[0]), "r"(b[1]));
}

// ------------------- transpose: dst(K x N) = src(N x K)^T -------------------
__global__ void k_transp(const float* __restrict__ src, float* __restrict__ dst,
                         int N, int K) {
    int o = blockIdx.x * blockDim.x + threadIdx.x;
    if (o >= N * K) return;
    int k = o / N, n = o % N;
    dst[o] = src[n * K + k];
}

// pack q|k|v|skip weights (each 128x128 row-major) into g_wcT[k*512+n] + bias
__global__ void k_packw(const float* __restrict__ wq, const float* __restrict__ wk,
                        const float* __restrict__ wv, const float* __restrict__ ws,
                        const float* __restrict__ bq, const float* __restrict__ bk,
                        const float* __restrict__ bv, const float* __restrict__ bs) {
    int o = blockIdx.x * blockDim.x + threadIdx.x;     // < 128*512
    if (o >= 128 * 512) return;
    int k = o >> 9, n = o & 511;
    int grp = n >> 7, r = n & 127;
    const float* w = (grp == 0) ? wq : (grp == 1) ? wk : (grp == 2) ? wv : ws;
    g_wcT[o] = w[r * 128 + k];
    if (k == 0) {
        const float* b = (grp == 0) ? bq : (grp == 1) ? bk : (grp == 2) ? bv : bs;
        g_bc[n] = b[r];
    }
}

// ------------------- zero touched agg entries -------------------
__global__ void k_zero(const int* __restrict__ sids, const int* __restrict__ dids) {
    int i = blockIdx.x;
    int sid = sids[i], did = dids[i];
    for (int t = threadIdx.x; t < MSG; t += blockDim.x) {
        g_aggS[sid * MSG + t] = 0.f;
        g_aggD[did * MSG + t] = 0.f;
    }
    if (threadIdx.x == 0) { g_cntS[sid] = 0.f; g_cntD[did] = 0.f; }
}

// ------------------- messages + scatter-sum -------------------
__global__ void __launch_bounds__(128) k_msg(
    const int* __restrict__ et, const int* __restrict__ sids,
    const float* __restrict__ smask, const int* __restrict__ dids,
    const float* __restrict__ dmask, const int* __restrict__ eids,
    const float* __restrict__ eemb, const float* __restrict__ emask,
    const float* __restrict__ ts, const float* __restrict__ last_update,
    const float* __restrict__ memory, const float* __restrict__ time_w,
    const float* __restrict__ time_b)
{
    int i = blockIdx.x, h = threadIdx.x;
    float em = emask[i], sm = smask[i], dm = dmask[i];
    int   etv = et[i];
    float tsv = ts[i];
    float el  = last_update[eids[i]];
    float rel = tsv - el * dm;
    float isn = (etv == 3 || etv == 4) ? 1.f : 0.f;
    float targ = tsv * isn + rel * dm;
    float cosv = cosf(targ * time_w[h] + time_b[h]) * em;
    int sid = sids[i], did = dids[i];
    float sv = memory[sid * H + h] * sm;
    float dv = memory[did * H + h] * dm;
    float ev = eemb[i * H + h];
    float typ = (float)etv;

    float* aS = g_aggS + sid * MSG;
    atomicAdd(aS + 0 * H + h, typ  * em);
    atomicAdd(aS + 1 * H + h, sv   * em);
    atomicAdd(aS + 2 * H + h, dv   * em);
    atomicAdd(aS + 3 * H + h, cosv * em);
    atomicAdd(aS + 4 * H + h, ev   * em);
    float* aD = g_aggD + did * MSG;
    atomicAdd(aD + 0 * H + h, typ  * dm);
    atomicAdd(aD + 1 * H + h, dv   * dm);
    atomicAdd(aD + 2 * H + h, sv   * dm);
    atomicAdd(aD + 3 * H + h, cosv * dm);
    atomicAdd(aD + 4 * H + h, ev   * dm);
    if (h == 0) { atomicAdd(&g_cntS[sid], 1.f); atomicAdd(&g_cntD[did], 1.f); }
}

// ------------------- gather GRU inputs -------------------
__global__ void __launch_bounds__(128) k_build_xh(
    const int* __restrict__ sids, const int* __restrict__ dids,
    const float* __restrict__ memory)
{
    int r = blockIdx.x;
    bool isS = r < EVT;
    int i = isS ? r : r - EVT;
    int id = isS ? sids[i] : dids[i];
    const float* agg = isS ? g_aggS : g_aggD;
    const float* cnt = isS ? g_cntS : g_cntD;
    float inv = 1.f / fmaxf(cnt[id], 1.f);
    for (int t = threadIdx.x; t < MSG; t += blockDim.x)
        g_X[r * MSG + t] = agg[id * MSG + t] * inv;
    for (int t = threadIdx.x; t < H; t += blockDim.x)
        g_Hst[r * H + t] = memory[id * H + t];
}

// ------------------- tf32 tensor-core GEMM: C(MxN)=A(MxK)@WT(KxN)+bias -------------------
__global__ void __launch_bounds__(256, 2) k_gemm_tc(
    const float* __restrict__ A, const float* __restrict__ WT,
    const float* __restrict__ bias, float* __restrict__ C,
    int M, int K, int N)
{
    int row0 = blockIdx.x * 128;
    if (row0 >= M) return;
    int col0 = blockIdx.y * 128;
    __shared__ unsigned sA[128 * 36];
    __shared__ unsigned sW[32 * 136];
    int tid = threadIdx.x, lane = tid & 31, wid = tid >> 5;
    int wm = wid & 3, wn = wid >> 2;
    int gid = lane >> 2, tig = lane & 3;

    float acc[2][8][4];
#pragma unroll
    for (int mt = 0; mt < 2; mt++)
#pragma unroll
        for (int nt = 0; nt < 8; nt++)
#pragma unroll
            for (int c = 0; c < 4; c++) acc[mt][nt][c] = 0.f;

    for (int kc = 0; kc < K; kc += 32) {
#pragma unroll
        for (int l = 0; l < 4; l++) {
            int idx = tid + l * 256;
            int row = idx >> 3, c4 = (idx & 7) * 4;
            float4 v = make_float4(0.f, 0.f, 0.f, 0.f);
            int r = row0 + row;
            if (r < M) v = *(const float4*)&A[(size_t)r * K + kc + c4];
            uint4 t;
            t.x = f2tf32(v.x); t.y = f2tf32(v.y);
            t.z = f2tf32(v.z); t.w = f2tf32(v.w);
            *(uint4*)&sA[row * 36 + c4] = t;
        }
#pragma unroll
        for (int l = 0; l < 4; l++) {
            int idx = tid + l * 256;
            int k = idx >> 5, n4 = (idx & 31) * 4;
            float4 v = *(const float4*)&WT[(size_t)(kc + k) * N + col0 + n4];
            uint4 t;
            t.x = f2tf32(v.x); t.y = f2tf32(v.y);
            t.z = f2tf32(v.z); t.w = f2tf32(v.w);
            *(uint4*)&sW[k * 136 + n4] = t;
        }
        __syncthreads();
#pragma unroll
        for (int k8 = 0; k8 < 32; k8 += 8) {
            unsigned a[2][4];
#pragma unroll
            for (int mt = 0; mt < 2; mt++) {
                int r = wm * 32 + mt * 16;
                a[mt][0] = sA[(r + gid    ) * 36 + k8 + tig    ];
                a[mt][1] = sA[(r + gid + 8) * 36 + k8 + tig    ];
                a[mt][2] = sA[(r + gid    ) * 36 + k8 + tig + 4];
                a[mt][3] = sA[(r + gid + 8) * 36 + k8 + tig + 4];
            }
#pragma unroll
            for (int nt = 0; nt < 8; nt++) {
                int n = wn * 64 + nt * 8 + gid;
                unsigned b[2];
                b[0] = sW[(k8 + tig    ) * 136 + n];
                b[1] = sW[(k8 + tig + 4) * 136 + n];
                mma_tf32(acc[0][nt], a[0], b);
                mma_tf32(acc[1][nt], a[1], b);
            }
        }
        __syncthreads();
    }
#pragma unroll
    for (int mt = 0; mt < 2; mt++) {
#pragma unroll
        for (int nt = 0; nt < 8; nt++) {
            int col = col0 + wn * 64 + nt * 8 + tig * 2;
            float b0 = 0.f, b1 = 0.f;
            if (bias) { b0 = bias[col]; b1 = bias[col + 1]; }
            int r0 = row0 + wm * 32 + mt * 16 + gid;
            if (r0 < M) {
                float2 o = make_float2(acc[mt][nt][0] + b0, acc[mt][nt][1] + b1);
                *(float2*)&C[(size_t)r0 * N + col] = o;
            }
            if (r0 + 8 < M) {
                float2 o = make_float2(acc[mt][nt][2] + b0, acc[mt][nt][3] + b1);
                *(float2*)&C[(size_t)(r0 + 8) * N + col] = o;
            }
        }
    }
}

// ------------------- fused E-GEMM: A built on the fly (cos | EF gather) -------------------
// A row u: cols [0,128) = cos(urelt[u]*tw+tb), cols [128,256) = EF[list[u]].
// K=256, N=128. M = g_ucount (dynamic).
__global__ void __launch_bounds__(256, 2) k_egemm(
    const float* __restrict__ EF, const float* __restrict__ tw,
    const float* __restrict__ tb, const float* __restrict__ WT,
    float* __restrict__ C)
{
    int M = g_ucount;
    int row0 = blockIdx.x * 128;
    if (row0 >= M) return;
    __shared__ unsigned sA[128 * 36];
    __shared__ unsigned sW[32 * 136];
    int tid = threadIdx.x, lane = tid & 31, wid = tid >> 5;
    int wm = wid & 3, wn = wid >> 2;
    int gid = lane >> 2, tig = lane & 3;

    float acc[2][8][4];
#pragma unroll
    for (int mt = 0; mt < 2; mt++)
#pragma unroll
        for (int nt = 0; nt < 8; nt++)
#pragma unroll
            for (int c = 0; c < 4; c++) acc[mt][nt][c] = 0.f;

    for (int kc = 0; kc < 256; kc += 32) {
#pragma unroll
        for (int l = 0; l < 4; l++) {
            int idx = tid + l * 256;
            int row = idx >> 3, c4 = (idx & 7) * 4;
            int r = row0 + row;
            float4 v = make_float4(0.f, 0.f, 0.f, 0.f);
            if (r < M) {
                int col = kc + c4;
                if (col < 128) {
                    float relt = g_urelt[r];
                    v.x = __cosf(relt * tw[col    ] + tb[col    ]);
                    v.y = __cosf(relt * tw[col + 1] + tb[col + 1]);
                    v.z = __cosf(relt * tw[col + 2] + tb[col + 2]);
                    v.w = __cosf(relt * tw[col + 3] + tb[col + 3]);
                } else {
                    int e = g_list[r];
                    v = *(const float4*)&EF[(size_t)e * H + col - 128];
                }
            }
            uint4 t;
            t.x = f2tf32(v.x); t.y = f2tf32(v.y);
            t.z = f2tf32(v.z); t.w = f2tf32(v.w);
            *(uint4*)&sA[row * 36 + c4] = t;
        }
#pragma unroll
        for (int l = 0; l < 4; l++) {
            int idx = tid + l * 256;
            int k = idx >> 5, n4 = (idx & 31) * 4;
            float4 v = *(const float4*)&WT[(size_t)(kc + k) * 128 + n4];
            uint4 t;
            t.x = f2tf32(v.x); t.y = f2tf32(v.y);
            t.z = f2tf32(v.z); t.w = f2tf32(v.w);
            *(uint4*)&sW[k * 136 + n4] = t;
        }
        __syncthreads();
#pragma unroll
        for (int k8 = 0; k8 < 32; k8 += 8) {
            unsigned a[2][4];
#pragma unroll
            for (int mt = 0; mt < 2; mt++) {
                int r = wm * 32 + mt * 16;
                a[mt][0] = sA[(r + gid    ) * 36 + k8 + tig    ];
                a[mt][1] = sA[(r + gid + 8) * 36 + k8 + tig    ];
                a[mt][2] = sA[(r + gid    ) * 36 + k8 + tig + 4];
                a[mt][3] = sA[(r + gid + 8) * 36 + k8 + tig + 4];
            }
#pragma unroll
            for (int nt = 0; nt < 8; nt++) {
                int n = wn * 64 + nt * 8 + gid;
                unsigned b[2];
                b[0] = sW[(k8 + tig    ) * 136 + n];
                b[1] = sW[(k8 + tig + 4) * 136 + n];
                mma_tf32(acc[0][nt], a[0], b);
                mma_tf32(acc[1][nt], a[1], b);
            }
        }
        __syncthreads();
    }
#pragma unroll
    for (int mt = 0; mt < 2; mt++) {
#pragma unroll
        for (int nt = 0; nt < 8; nt++) {
            int col = wn * 64 + nt * 8 + tig * 2;
            int r0 = row0 + wm * 32 + mt * 16 + gid;
            if (r0 < M) {
                float2 o = make_float2(acc[mt][nt][0], acc[mt][nt][1]);
                *(float2*)&C[(size_t)r0 * 128 + col] = o;
            }
            if (r0 + 8 < M) {
                float2 o = make_float2(acc[mt][nt][2], acc[mt][nt][3]);
                *(float2*)&C[(size_t)(r0 + 8) * 128 + col] = o;
            }
        }
    }
}

// ------------------- GRU activation -------------------
__global__ void k_gru_act() {
    int idx = blockIdx.x * blockDim.x + threadIdx.x;
    int r = idx >> 7, h = idx & 127;
    float ir = g_GI[r * 384 + h];
    float iz = g_GI[r * 384 + 128 + h];
    float in_ = g_GI[r * 384 + 256 + h];
    float hr = g_GH[r * 384 + h];
    float hz = g_GH[r * 384 + 128 + h];
    float hn = g_GH[r * 384 + 256 + h];
    float rr = 1.f / (1.f + expf(-(ir + hr)));
    float zz = 1.f / (1.f + expf(-(iz + hz)));
    float nn = tanhf(in_ + rr * hn);
    float h0 = g_Hst[idx];
    g_newMem[idx] = (1.f - zz) * nn + zz * h0;
}

// ------------------- override tags -------------------
__global__ void k_tag(const int* __restrict__ ids, int sgn) {
    int t = blockIdx.x * blockDim.x + threadIdx.x;
    if (t < EVT) g_tag[ids[t]] = (sgn > 0) ? (t + 1) : -(t + 1);
}

// ------------------- unique-eid flagging -------------------
__global__ void k_flag(const int* __restrict__ eids) {
    int j = blockIdx.x * blockDim.x + threadIdx.x;
    if (j >= NE) return;
    int e = eids[j];
    if (atomicExch(&g_flag[e], 1) == 0) {
        int u = atomicAdd(&g_ucount, 1);
        g_list[u] = e;
        g_slot[e] = u;
    }
}
__global__ void k_unflag(const int* __restrict__ eids) {
    int j = blockIdx.x * blockDim.x + threadIdx.x;
    if (j < NE) g_flag[eids[j]] = 0;
    if (j == 0) g_ucount = 0;
}
__global__ void k_urelt(const float* __restrict__ last_update,
                        const void* __restrict__ timep) {
    int u = blockIdx.x * blockDim.x + threadIdx.x;
    if (u >= g_ucount) return;
    g_urelt[u] = get_time(timep) - last_update[g_list[u]];
}

// ------------------- x = node_features[nid] + updated_memory[nid] -------------------
__global__ void k_x(const int* __restrict__ node_ids,
                    const float* __restrict__ node_features,
                    const float* __restrict__ memory)
{
    int idx = blockIdx.x * blockDim.x + threadIdx.x;
    int r = idx >> 7, h = idx & 127;
    int gid = node_ids[r];
    int tg = g_tag[gid];
    float mv = (tg > 0) ? g_newMem[(tg - 1) * H + h]
             : (tg < 0) ? g_newMem[(EVT + (-tg - 1)) * H + h]
                        : memory[gid * H + h];
    g_x[idx] = node_features[gid * H + h] + mv;
}

// ------------------- counting sort by dst -------------------
__global__ void k_cnt0() {
    int i = blockIdx.x * blockDim.x + threadIdx.x;
    if (i < NN) g_cnt[i] = 0;
}
__global__ void k_hist(const int* __restrict__ ei) {
    int j = blockIdx.x * blockDim.x + threadIdx.x;
    if (j < NE) atomicAdd(&g_cnt[ei[NE + j]], 1);
}
__global__ void __launch_bounds__(512) k_scan() {   // single block
    __shared__ int ssum[512];
    int t = threadIdx.x;
    const int CH = 40;                              // 512*40 >= 20000
    int base = t * CH;
    int loc = 0;
#pragma unroll 4
    for (int i = 0; i < CH; i++) {
        int idx = base + i;
        if (idx < NN) loc += g_cnt[idx];
    }
    ssum[t] = loc;
    __syncthreads();
    // Hillis-Steele inclusive scan
    for (int off = 1; off < 512; off <<= 1) {
        int v = (t >= off) ? ssum[t - off] : 0;
        __syncthreads();
        ssum[t] += v;
        __syncthreads();
    }
    int run = ssum[t] - loc;                        // exclusive prefix
    for (int i = 0; i < CH; i++) {
        int idx = base + i;
        if (idx < NN) {
            g_off[idx] = run;
            g_cur[idx] = run;
            run += g_cnt[idx];
        }
    }
    if (t == 511) g_off[NN] = ssum[511];
}
__global__ void k_scatter(const int* __restrict__ ei, const int* __restrict__ eids) {
    int j = blockIdx.x * blockDim.x + threadIdx.x;
    if (j >= NE) return;
    int d = ei[NE + j];
    int pos = atomicAdd(&g_cur[d], 1);
    g_ss[pos] = ei[j];
    g_sd[pos] = d;
    g_su[pos] = g_slot[eids[j]];
}

// ------------------- alpha per sorted edge -------------------
__global__ void __launch_bounds__(256) k_alpha() {
    int warp = threadIdx.x >> 5, lane = threadIdx.x & 31;
    int j = blockIdx.x * 8 + warp;
    int s = g_ss[j], d = g_sd[j], u = g_su[j];
    float4 qv = *(const float4*)&g_qkvs[(size_t)d * 512 +       lane * 4];
    float4 kv = *(const float4*)&g_qkvs[(size_t)s * 512 + 128 + lane * 4];
    float4 e4 = *(const float4*)&g_Ec  [(size_t)u * H   +       lane * 4];
    float p = qv.x * (kv.x + e4.x) + qv.y * (kv.y + e4.y)
            + qv.z * (kv.z + e4.z) + qv.w * (kv.w + e4.w);
#pragma unroll
    for (int o = 16; o; o >>= 1) p += __shfl_xor_sync(0xffffffffu, p, o);
    if (lane == 0) g_salpha[j] = p * 0.08838834764831845f;   // 1/sqrt(128)
}

// ------------------- per-node softmax + weighted sum + skip, one warp / node -------------------
__global__ void __launch_bounds__(256) k_reduce(float* __restrict__ out) {
    int warp = threadIdx.x >> 5, lane = threadIdx.x & 31;
    int d = blockIdx.x * 8 + warp;
    if (d >= NN) return;
    int off0 = g_off[d], off1 = g_off[d + 1];

    float m = -1e30f;
    for (int i = off0 + lane; i < off1; i += 32) m = fmaxf(m, g_salpha[i]);
#pragma unroll
    for (int o = 16; o; o >>= 1) m = fmaxf(m, __shfl_xor_sync(0xffffffffu, m, o));

    float den = 0.f;
    for (int i = off0 + lane; i < off1; i += 32) den += __expf(g_salpha[i] - m);
#pragma unroll
    for (int o = 16; o; o >>= 1) den += __shfl_xor_sync(0xffffffffu, den, o);
    float rden = 1.f / fmaxf(den, 1e-16f);

    float4 acc = make_float4(0.f, 0.f, 0.f, 0.f);
    for (int i = off0; i < off1; i++) {
        float p = __expf(g_salpha[i] - m) * rden;
        int s = g_ss[i], u = g_su[i];
        float4 vv = *(const float4*)&g_qkvs[(size_t)s * 512 + 256 + lane * 4];
        float4 e4 = *(const float4*)&g_Ec  [(size_t)u * H   +       lane * 4];
        acc.x += p * (vv.x + e4.x);
        acc.y += p * (vv.y + e4.y);
        acc.z += p * (vv.z + e4.z);
        acc.w += p * (vv.w + e4.w);
    }
    float4 sk = *(const float4*)&g_qkvs[(size_t)d * 512 + 384 + lane * 4];
    float4 o4 = make_float4(sk.x + acc.x, sk.y + acc.y, sk.z + acc.z, sk.w + acc.w);
    *(float4*)&out[(size_t)d * H + lane * 4] = o4;
}

// ------------------- host -------------------
static float* symf(const void* s) {
    void* p = nullptr;
    cudaGetSymbolAddress(&p, s);
    return (float*)p;
}

extern "C" void kernel_launch(void* const* d_in, const int* in_sizes, int n_in,
                              void* d_out, int out_size)
{
    const int*   event_type_ids = (const int*)  d_in[0];
    const int*   src_ids        = (const int*)  d_in[1];
    const float* src_mask       = (const float*)d_in[2];
    const int*   dst_ids        = (const int*)  d_in[3];
    const float* dst_mask       = (const float*)d_in[4];
    const int*   event_edge_ids = (const int*)  d_in[5];
    const float* event_emb      = (const float*)d_in[6];
    const float* event_mask     = (const float*)d_in[7];
    const float* event_ts       = (const float*)d_in[8];
    const int*   node_ids       = (const int*)  d_in[9];
    const int*   edge_ids       = (const int*)  d_in[10];
    const int*   edge_index     = (const int*)  d_in[11];
    const void*  timep          =               d_in[12];
    const float* memory         = (const float*)d_in[13];
    const float* last_update    = (const float*)d_in[14];
    const float* node_features  = (const float*)d_in[15];
    const float* edge_features  = (const float*)d_in[16];
    const float* time_w         = (const float*)d_in[17];
    const float* time_b         = (const float*)d_in[18];
    const float* gru_w_ih       = (const float*)d_in[19];
    const float* gru_w_hh       = (const float*)d_in[20];
    const float* gru_b_ih       = (const float*)d_in[21];
    const float* gru_b_hh       = (const float*)d_in[22];
    const float* wq             = (const float*)d_in[23];
    const float* bq             = (const float*)d_in[24];
    const float* wk             = (const float*)d_in[25];
    const float* bk             = (const float*)d_in[26];
    const float* wv             = (const float*)d_in[27];
    const float* bv             = (const float*)d_in[28];
    const float* we             = (const float*)d_in[29];
    const float* wskip          = (const float*)d_in[30];
    const float* bskip          = (const float*)d_in[31];
    float* out = (float*)d_out;

    float* pX    = symf(g_X);    float* pH    = symf(g_Hst);
    float* pGI   = symf(g_GI);   float* pGH   = symf(g_GH);
    float* pEc   = symf(g_Ec);   float* px    = symf(g_x);
    float* pqkvs = symf(g_qkvs);
    float* pwih  = symf(g_wihT); float* pwhh  = symf(g_whhT);
    float* pwe   = symf(g_weT);  float* pwc   = symf(g_wcT);
    float* pbc   = symf(g_bc);

    // weight prep
    k_transp<<<(384 * 640 + 255) / 256, 256>>>(gru_w_ih, pwih, 384, 640);
    k_transp<<<(384 * 128 + 255) / 256, 256>>>(gru_w_hh, pwhh, 384, 128);
    k_transp<<<(128 * 256 + 255) / 256, 256>>>(we,       pwe,  128, 256);
    k_packw<<<(128 * 512 + 255) / 256, 256>>>(wq, wk, wv, wskip, bq, bk, bv, bskip);

    // unique-eid flagging + dst counting sort
    k_flag<<<(NE + 255) / 256, 256>>>(edge_ids);
    k_cnt0<<<(NN + 255) / 256, 256>>>();
    k_hist<<<(NE + 255) / 256, 256>>>(edge_index);
    k_scan<<<1, 512>>>();
    k_scatter<<<(NE + 255) / 256, 256>>>(edge_index, edge_ids);
    k_urelt<<<(MAXE + 255) / 256, 256>>>(last_update, timep);

    // message + aggregation
    k_zero<<<EVT, 256>>>(src_ids, dst_ids);
    k_msg<<<EVT, 128>>>(event_type_ids, src_ids, src_mask, dst_ids, dst_mask,
                        event_edge_ids, event_emb, event_mask, event_ts,
                        last_update, memory, time_w, time_b);
    k_build_xh<<<2 * EVT, 128>>>(src_ids, dst_ids, memory);

    // GRU (tf32 tensor-core GEMMs)
    k_gemm_tc<<<dim3(64, 3), 256>>>(pX, pwih, gru_b_ih, pGI, 2 * EVT, 640, 384);
    k_gemm_tc<<<dim3(64, 3), 256>>>(pH, pwhh, gru_b_hh, pGH, 2 * EVT, 128, 384);
    k_gru_act<<<(2 * EVT * H) / 256, 256>>>();
    k_tag<<<16, 256>>>(src_ids, 1);
    k_tag<<<16, 256>>>(dst_ids, -1);   // dst overrides src

    // fused edge-attr E-GEMM over unique eids
    k_egemm<<<(MAXE + 127) / 128, 256>>>(edge_features, time_w, time_b, pwe, pEc);

    // node features + fused q|k|v|skip GEMM
    k_x<<<(NN * H) / 256, 256>>>(node_ids, node_features, memory);
    k_gemm_tc<<<dim3((NN + 127) / 128, 4), 256>>>(px, pwc, pbc, pqkvs, NN, 128, 512);

    // attention: sorted alpha + per-node reduce (no atomics)
    k_alpha<<<NE / 8, 256>>>();
    k_reduce<<<(NN + 7) / 8, 256>>>(out);

    // reset flags/count for next replay (graph-idempotent)
    k_unflag<<<(NE + 255) / 256, 256>>>(edge_ids);
}

// round 11
// speedup vs baseline: 4.0741x; 1.1572x over previous
#include <cuda_runtime.h>
#include <math.h>

#define H      128
#define EVT    4096
#define NN     20000
#define NE     320000
#define MAXN   100000
#define MAXE   300000
#define MSG    640
#define DSTBIT (1 << 30)

// ------------------- device scratch (static, allowed) -------------------
__device__ float    g_aggS[MAXN * MSG];
__device__ float    g_aggD[MAXN * MSG];
__device__ float    g_cntS[MAXN];
__device__ float    g_cntD[MAXN];
__device__ float    g_X   [2 * EVT * MSG];
__device__ float    g_Hst [2 * EVT * H];
__device__ float    g_GI  [2 * EVT * 384];
__device__ float    g_GH  [2 * EVT * 384];
__device__ float    g_newMem[2 * EVT * H];
__device__ int      g_tag [MAXN];        // 0-init; monotone atomicMax keys
// unique-edge machinery
__device__ int      g_flag[MAXE];        // 0-init; cleared at end of each launch
__device__ int      g_list[MAXE];
__device__ int      g_slot[MAXE];
__device__ int      g_ucount;            // 0-init; reset at end of each launch
__device__ float    g_urelt[MAXE];
__device__ float    g_Ec  [MAXE * H];
__device__ float    g_x   [NN * H];
__device__ float    g_qkvs[NN * 512];    // [q | k | v | skip]
// dst-sorted edge machinery
__device__ int      g_cnt [NN];
__device__ int      g_off [NN + 1];
__device__ int      g_cur [NN];
__device__ int      g_ss  [NE];          // src, sorted by dst
__device__ int      g_su  [NE];          // unique-eid slot, sorted by dst
// weights
__device__ float    g_wihT[640 * 384];
__device__ float    g_whhT[128 * 384];
__device__ float    g_weT [256 * 128];
__device__ float    g_wcT [128 * 512];
__device__ float    g_bc  [512];

// ------------------- helpers -------------------
__device__ __forceinline__ float get_time(const void* p) {
    int iv = *(const int*)p;
    if (iv > -1000000 && iv < 1000000) return (float)iv;
    return *(const float*)p;
}
__device__ __forceinline__ unsigned f2tf32(float f) {
    unsigned r;
    asm("cvt.rna.tf32.f32 %0, %1;" : "=r"(r) : "f"(f));
    return r;
}
__device__ __forceinline__ void mma_tf32(float* d, const unsigned* a, const unsigned* b) {
    asm("mma.sync.aligned.m16n8k8.row.col.f32.tf32.tf32.f32 "
        "{%0,%1,%2,%3}, {%4,%5,%6,%7}, {%8,%9}, {%0,%1,%2,%3};"
        : "+f"(d[0]), "+f"(d[1]), "+f"(d[2]), "+f"(d[3])
        : "r"(a[0]), "r"(a[1]), "r"(a[2]), "r"(a[3]), "r"(b[0]), "r"(b[1]));
}

// ------------------- K1: fused prep (all independent) -------------------
// blocks: [0,960) transp wih | [960,1152) transp whh | [1152,1280) transp we
//         [1280,1536) packw | [1536,2786) flag | [2786,2865) cnt0 | [2865,6961) zero
__global__ void __launch_bounds__(256) k_prep(
    const float* __restrict__ gru_w_ih, const float* __restrict__ gru_w_hh,
    const float* __restrict__ we,
    const float* __restrict__ wq, const float* __restrict__ wk,
    const float* __restrict__ wv, const float* __restrict__ ws,
    const float* __restrict__ bq, const float* __restrict__ bk,
    const float* __restrict__ bv, const float* __restrict__ bs,
    const int* __restrict__ eids,
    const int* __restrict__ sids, const int* __restrict__ dids)
{
    int b = blockIdx.x, tid = threadIdx.x;
    if (b < 960) {                       // wihT: (384x640)^T
        int o = b * 256 + tid;           // < 245760
        int k = o / 384, n = o % 384;
        g_wihT[o] = gru_w_ih[n * 640 + k];
    } else if (b < 1152) {               // whhT: (384x128)^T
        int o = (b - 960) * 256 + tid;   // < 49152
        int k = o / 384, n = o % 384;
        g_whhT[o] = gru_w_hh[n * 128 + k];
    } else if (b < 1280) {               // weT: (128x256)^T
        int o = (b - 1152) * 256 + tid;  // < 32768
        int k = o / 128, n = o % 128;
        g_weT[o] = we[n * 256 + k];
    } else if (b < 1536) {               // packw
        int o = (b - 1280) * 256 + tid;  // < 65536
        int k = o >> 9, n = o & 511;
        int grp = n >> 7, r = n & 127;
        const float* w = (grp == 0) ? wq : (grp == 1) ? wk : (grp == 2) ? wv : ws;
        g_wcT[o] = w[r * 128 + k];
        if (k == 0) {
            const float* bb = (grp == 0) ? bq : (grp == 1) ? bk : (grp == 2) ? bv : bs;
            g_bc[n] = bb[r];
        }
    } else if (b < 2786) {               // flag unique eids
        int j = (b - 1536) * 256 + tid;
        if (j < NE) {
            int e = eids[j];
            if (atomicExch(&g_flag[e], 1) == 0) {
                int u = atomicAdd(&g_ucount, 1);
                g_list[u] = e;
                g_slot[e] = u;
            }
        }
    } else if (b < 2865) {               // cnt0
        int i = (b - 2786) * 256 + tid;
        if (i < NN) g_cnt[i] = 0;
    } else {                             // zero agg rows (4096 blocks)
        int i = b - 2865;
        int sid = sids[i], did = dids[i];
        for (int t = tid; t < MSG; t += 256) {
            g_aggS[sid * MSG + t] = 0.f;
            g_aggD[did * MSG + t] = 0.f;
        }
        if (tid == 0) { g_cntS[sid] = 0.f; g_cntD[did] = 0.f; }
    }
}

// ------------------- K2: msg + hist + urelt -------------------
// blocks: [0,2048) msg (2 events/block) | [2048,4548) hist | [4548,6892) urelt
__global__ void __launch_bounds__(256) k_phase2(
    const int* __restrict__ et, const int* __restrict__ sids,
    const float* __restrict__ smask, const int* __restrict__ dids,
    const float* __restrict__ dmask, const int* __restrict__ eids,
    const float* __restrict__ eemb, const float* __restrict__ emask,
    const float* __restrict__ ts, const float* __restrict__ last_update,
    const float* __restrict__ memory, const float* __restrict__ time_w,
    const float* __restrict__ time_b, const int* __restrict__ ei,
    const void* __restrict__ timep)
{
    int b = blockIdx.x, tid = threadIdx.x;
    if (b < 2048) {
        int i = b * 2 + (tid >> 7);
        int h = tid & 127;
        float em = emask[i], sm = smask[i], dm = dmask[i];
        int   etv = et[i];
        float tsv = ts[i];
        float el  = last_update[eids[i]];
        float rel = tsv - el * dm;
        float isn = (etv == 3 || etv == 4) ? 1.f : 0.f;
        float targ = tsv * isn + rel * dm;
        float cosv = cosf(targ * time_w[h] + time_b[h]) * em;
        int sid = sids[i], did = dids[i];
        float sv = memory[sid * H + h] * sm;
        float dv = memory[did * H + h] * dm;
        float ev = eemb[i * H + h];
        float typ = (float)etv;
        float* aS = g_aggS + sid * MSG;
        atomicAdd(aS + 0 * H + h, typ  * em);
        atomicAdd(aS + 1 * H + h, sv   * em);
        atomicAdd(aS + 2 * H + h, dv   * em);
        atomicAdd(aS + 3 * H + h, cosv * em);
        atomicAdd(aS + 4 * H + h, ev   * em);
        float* aD = g_aggD + did * MSG;
        atomicAdd(aD + 0 * H + h, typ  * dm);
        atomicAdd(aD + 1 * H + h, dv   * dm);
        atomicAdd(aD + 2 * H + h, sv   * dm);
        atomicAdd(aD + 3 * H + h, cosv * dm);
        atomicAdd(aD + 4 * H + h, ev   * dm);
        if (h == 0) { atomicAdd(&g_cntS[sid], 1.f); atomicAdd(&g_cntD[did], 1.f); }
    } else if (b < 4548) {
        int j = (b - 2048) * 256 + tid;
        if (j < NE) atomicAdd(&g_cnt[ei[NE + j]], 1);
    } else {
        int u = (b - 4548) * 256 + tid;
        if (u < g_ucount)
            g_urelt[u] = get_time(timep) - last_update[g_list[u]];
    }
}

// ------------------- K3: build_xh + scan -------------------
// blocks: [0, 8192) build_xh | block 8192 = scan (512 threads)
__global__ void __launch_bounds__(512) k_phase3(
    const int* __restrict__ sids, const int* __restrict__ dids,
    const float* __restrict__ memory)
{
    int b = blockIdx.x, t = threadIdx.x;
    if (b < 2 * EVT) {
        bool isS = b < EVT;
        int i = isS ? b : b - EVT;
        int id = isS ? sids[i] : dids[i];
        const float* agg = isS ? g_aggS : g_aggD;
        const float* cnt = isS ? g_cntS : g_cntD;
        float inv = 1.f / fmaxf(cnt[id], 1.f);
        for (int c = t; c < MSG; c += 512)
            g_X[b * MSG + c] = agg[id * MSG + c] * inv;
        if (t < H)
            g_Hst[b * H + t] = memory[id * H + t];
    } else {
        // single-block scan of g_cnt -> g_off / g_cur
        __shared__ int ssum[512];
        const int CH = 40;
        int base = t * CH;
        int loc = 0;
#pragma unroll 4
        for (int i = 0; i < CH; i++) {
            int idx = base + i;
            if (idx < NN) loc += g_cnt[idx];
        }
        ssum[t] = loc;
        __syncthreads();
        for (int off = 1; off < 512; off <<= 1) {
            int v = (t >= off) ? ssum[t - off] : 0;
            __syncthreads();
            ssum[t] += v;
            __syncthreads();
        }
        int run = ssum[t] - loc;
        for (int i = 0; i < CH; i++) {
            int idx = base + i;
            if (idx < NN) {
                g_off[idx] = run;
                g_cur[idx] = run;
                run += g_cnt[idx];
            }
        }
        if (t == 511) g_off[NN] = ssum[511];
    }
}

// ------------------- tf32 GEMM (generic) -------------------
__global__ void __launch_bounds__(256, 2) k_gemm_tc(
    const float* __restrict__ A, const float* __restrict__ WT,
    const float* __restrict__ bias, float* __restrict__ C,
    int M, int K, int N)
{
    int row0 = blockIdx.x * 128;
    if (row0 >= M) return;
    int col0 = blockIdx.y * 128;
    __shared__ unsigned sA[128 * 36];
    __shared__ unsigned sW[32 * 136];
    int tid = threadIdx.x, lane = tid & 31, wid = tid >> 5;
    int wm = wid & 3, wn = wid >> 2;
    int gid = lane >> 2, tig = lane & 3;

    float acc[2][8][4];
#pragma unroll
    for (int mt = 0; mt < 2; mt++)
#pragma unroll
        for (int nt = 0; nt < 8; nt++)
#pragma unroll
            for (int c = 0; c < 4; c++) acc[mt][nt][c] = 0.f;

    for (int kc = 0; kc < K; kc += 32) {
#pragma unroll
        for (int l = 0; l < 4; l++) {
            int idx = tid + l * 256;
            int row = idx >> 3, c4 = (idx & 7) * 4;
            float4 v = make_float4(0.f, 0.f, 0.f, 0.f);
            int r = row0 + row;
            if (r < M) v = *(const float4*)&A[(size_t)r * K + kc + c4];
            uint4 t;
            t.x = f2tf32(v.x); t.y = f2tf32(v.y);
            t.z = f2tf32(v.z); t.w = f2tf32(v.w);
            *(uint4*)&sA[row * 36 + c4] = t;
        }
#pragma unroll
        for (int l = 0; l < 4; l++) {
            int idx = tid + l * 256;
            int k = idx >> 5, n4 = (idx & 31) * 4;
            float4 v = *(const float4*)&WT[(size_t)(kc + k) * N + col0 + n4];
            uint4 t;
            t.x = f2tf32(v.x); t.y = f2tf32(v.y);
            t.z = f2tf32(v.z); t.w = f2tf32(v.w);
            *(uint4*)&sW[k * 136 + n4] = t;
        }
        __syncthreads();
#pragma unroll
        for (int k8 = 0; k8 < 32; k8 += 8) {
            unsigned a[2][4];
#pragma unroll
            for (int mt = 0; mt < 2; mt++) {
                int r = wm * 32 + mt * 16;
                a[mt][0] = sA[(r + gid    ) * 36 + k8 + tig    ];
                a[mt][1] = sA[(r + gid + 8) * 36 + k8 + tig    ];
                a[mt][2] = sA[(r + gid    ) * 36 + k8 + tig + 4];
                a[mt][3] = sA[(r + gid + 8) * 36 + k8 + tig + 4];
            }
#pragma unroll
            for (int nt = 0; nt < 8; nt++) {
                int n = wn * 64 + nt * 8 + gid;
                unsigned b[2];
                b[0] = sW[(k8 + tig    ) * 136 + n];
                b[1] = sW[(k8 + tig + 4) * 136 + n];
                mma_tf32(acc[0][nt], a[0], b);
                mma_tf32(acc[1][nt], a[1], b);
            }
        }
        __syncthreads();
    }
#pragma unroll
    for (int mt = 0; mt < 2; mt++) {
#pragma unroll
        for (int nt = 0; nt < 8; nt++) {
            int col = col0 + wn * 64 + nt * 8 + tig * 2;
            float b0 = 0.f, b1 = 0.f;
            if (bias) { b0 = bias[col]; b1 = bias[col + 1]; }
            int r0 = row0 + wm * 32 + mt * 16 + gid;
            if (r0 < M) {
                float2 o = make_float2(acc[mt][nt][0] + b0, acc[mt][nt][1] + b1);
                *(float2*)&C[(size_t)r0 * N + col] = o;
            }
            if (r0 + 8 < M) {
                float2 o = make_float2(acc[mt][nt][2] + b0, acc[mt][nt][3] + b1);
                *(float2*)&C[(size_t)(r0 + 8) * N + col] = o;
            }
        }
    }
}

// ------------------- K4: both GRU GEMMs in one launch (z selects) -------------------
__global__ void __launch_bounds__(256, 2) k_gru_gemms(
    const float* __restrict__ b_ih, const float* __restrict__ b_hh)
{
    int z = blockIdx.z;
    const float* A    = z ? g_Hst  : g_X;
    const float* WT   = z ? g_whhT : g_wihT;
    const float* bias = z ? b_hh   : b_ih;
    float*       C    = z ? g_GH   : g_GI;
    int K = z ? 128 : 640;
    const int M = 2 * EVT, N = 384;

    int row0 = blockIdx.x * 128;
    int col0 = blockIdx.y * 128;
    __shared__ unsigned sA[128 * 36];
    __shared__ unsigned sW[32 * 136];
    int tid = threadIdx.x, lane = tid & 31, wid = tid >> 5;
    int wm = wid & 3, wn = wid >> 2;
    int gid = lane >> 2, tig = lane & 3;

    float acc[2][8][4];
#pragma unroll
    for (int mt = 0; mt < 2; mt++)
#pragma unroll
        for (int nt = 0; nt < 8; nt++)
#pragma unroll
            for (int c = 0; c < 4; c++) acc[mt][nt][c] = 0.f;

    for (int kc = 0; kc < K; kc += 32) {
#pragma unroll
        for (int l = 0; l < 4; l++) {
            int idx = tid + l * 256;
            int row = idx >> 3, c4 = (idx & 7) * 4;
            float4 v = *(const float4*)&A[(size_t)(row0 + row) * K + kc + c4];
            uint4 t;
            t.x = f2tf32(v.x); t.y = f2tf32(v.y);
            t.z = f2tf32(v.z); t.w = f2tf32(v.w);
            *(uint4*)&sA[row * 36 + c4] = t;
        }
#pragma unroll
        for (int l = 0; l < 4; l++) {
            int idx = tid + l * 256;
            int k = idx >> 5, n4 = (idx & 31) * 4;
            float4 v = *(const float4*)&WT[(size_t)(kc + k) * N + col0 + n4];
            uint4 t;
            t.x = f2tf32(v.x); t.y = f2tf32(v.y);
            t.z = f2tf32(v.z); t.w = f2tf32(v.w);
            *(uint4*)&sW[k * 136 + n4] = t;
        }
        __syncthreads();
#pragma unroll
        for (int k8 = 0; k8 < 32; k8 += 8) {
            unsigned a[2][4];
#pragma unroll
            for (int mt = 0; mt < 2; mt++) {
                int r = wm * 32 + mt * 16;
                a[mt][0] = sA[(r + gid    ) * 36 + k8 + tig    ];
                a[mt][1] = sA[(r + gid + 8) * 36 + k8 + tig    ];
                a[mt][2] = sA[(r + gid    ) * 36 + k8 + tig + 4];
                a[mt][3] = sA[(r + gid + 8) * 36 + k8 + tig + 4];
            }
#pragma unroll
            for (int nt = 0; nt < 8; nt++) {
                int n = wn * 64 + nt * 8 + gid;
                unsigned b[2];
                b[0] = sW[(k8 + tig    ) * 136 + n];
                b[1] = sW[(k8 + tig + 4) * 136 + n];
                mma_tf32(acc[0][nt], a[0], b);
                mma_tf32(acc[1][nt], a[1], b);
            }
        }
        __syncthreads();
    }
#pragma unroll
    for (int mt = 0; mt < 2; mt++) {
#pragma unroll
        for (int nt = 0; nt < 8; nt++) {
            int col = col0 + wn * 64 + nt * 8 + tig * 2;
            float b0 = bias[col], b1 = bias[col + 1];
            int r0 = row0 + wm * 32 + mt * 16 + gid;
            float2 o0 = make_float2(acc[mt][nt][0] + b0, acc[mt][nt][1] + b1);
            float2 o1 = make_float2(acc[mt][nt][2] + b0, acc[mt][nt][3] + b1);
            *(float2*)&C[(size_t)r0 * N + col] = o0;
            *(float2*)&C[(size_t)(r0 + 8) * N + col] = o1;
        }
    }
}

// ------------------- fused E-GEMM (A built on the fly: cos | EF gather) -------------------
__global__ void __launch_bounds__(256, 2) k_egemm(
    const float* __restrict__ EF, const float* __restrict__ tw,
    const float* __restrict__ tb, const float* __restrict__ WT,
    float* __restrict__ C)
{
    int M = g_ucount;
    int row0 = blockIdx.x * 128;
    if (row0 >= M) return;
    __shared__ unsigned sA[128 * 36];
    __shared__ unsigned sW[32 * 136];
    int tid = threadIdx.x, lane = tid & 31, wid = tid >> 5;
    int wm = wid & 3, wn = wid >> 2;
    int gid = lane >> 2, tig = lane & 3;

    float acc[2][8][4];
#pragma unroll
    for (int mt = 0; mt < 2; mt++)
#pragma unroll
        for (int nt = 0; nt < 8; nt++)
#pragma unroll
            for (int c = 0; c < 4; c++) acc[mt][nt][c] = 0.f;

    for (int kc = 0; kc < 256; kc += 32) {
#pragma unroll
        for (int l = 0; l < 4; l++) {
            int idx = tid + l * 256;
            int row = idx >> 3, c4 = (idx & 7) * 4;
            int r = row0 + row;
            float4 v = make_float4(0.f, 0.f, 0.f, 0.f);
            if (r < M) {
                int col = kc + c4;
                if (col < 128) {
                    float relt = g_urelt[r];
                    v.x = __cosf(relt * tw[col    ] + tb[col    ]);
                    v.y = __cosf(relt * tw[col + 1] + tb[col + 1]);
                    v.z = __cosf(relt * tw[col + 2] + tb[col + 2]);
                    v.w = __cosf(relt * tw[col + 3] + tb[col + 3]);
                } else {
                    int e = g_list[r];
                    v = *(const float4*)&EF[(size_t)e * H + col - 128];
                }
            }
            uint4 t;
            t.x = f2tf32(v.x); t.y = f2tf32(v.y);
            t.z = f2tf32(v.z); t.w = f2tf32(v.w);
            *(uint4*)&sA[row * 36 + c4] = t;
        }
#pragma unroll
        for (int l = 0; l < 4; l++) {
            int idx = tid + l * 256;
            int k = idx >> 5, n4 = (idx & 31) * 4;
            float4 v = *(const float4*)&WT[(size_t)(kc + k) * 128 + n4];
            uint4 t;
            t.x = f2tf32(v.x); t.y = f2tf32(v.y);
            t.z = f2tf32(v.z); t.w = f2tf32(v.w);
            *(uint4*)&sW[k * 136 + n4] = t;
        }
        __syncthreads();
#pragma unroll
        for (int k8 = 0; k8 < 32; k8 += 8) {
            unsigned a[2][4];
#pragma unroll
            for (int mt = 0; mt < 2; mt++) {
                int r = wm * 32 + mt * 16;
                a[mt][0] = sA[(r + gid    ) * 36 + k8 + tig    ];
                a[mt][1] = sA[(r + gid + 8) * 36 + k8 + tig    ];
                a[mt][2] = sA[(r + gid    ) * 36 + k8 + tig + 4];
                a[mt][3] = sA[(r + gid + 8) * 36 + k8 + tig + 4];
            }
#pragma unroll
            for (int nt = 0; nt < 8; nt++) {
                int n = wn * 64 + nt * 8 + gid;
                unsigned b[2];
                b[0] = sW[(k8 + tig    ) * 136 + n];
                b[1] = sW[(k8 + tig + 4) * 136 + n];
                mma_tf32(acc[0][nt], a[0], b);
                mma_tf32(acc[1][nt], a[1], b);
            }
        }
        __syncthreads();
    }
#pragma unroll
    for (int mt = 0; mt < 2; mt++) {
#pragma unroll
        for (int nt = 0; nt < 8; nt++) {
            int col = wn * 64 + nt * 8 + tig * 2;
            int r0 = row0 + wm * 32 + mt * 16 + gid;
            if (r0 < M) {
                float2 o = make_float2(acc[mt][nt][0], acc[mt][nt][1]);
                *(float2*)&C[(size_t)r0 * 128 + col] = o;
            }
            if (r0 + 8 < M) {
                float2 o = make_float2(acc[mt][nt][2], acc[mt][nt][3]);
                *(float2*)&C[(size_t)(r0 + 8) * 128 + col] = o;
            }
        }
    }
}

// ------------------- K6: gru_act + scatter + tag -------------------
// blocks: [0,4096) act | [4096,5346) scatter | [5346,5378) tag
__global__ void __launch_bounds__(256) k_phase4(
    const int* __restrict__ ei, const int* __restrict__ eids,
    const int* __restrict__ sids, const int* __restrict__ dids)
{
    int b = blockIdx.x, tid = threadIdx.x;
    if (b < 4096) {
        int idx = b * 256 + tid;            // < 8192*128
        int r = idx >> 7, h = idx & 127;
        float ir = g_GI[r * 384 + h];
        float iz = g_GI[r * 384 + 128 + h];
        float in_ = g_GI[r * 384 + 256 + h];
        float hr = g_GH[r * 384 + h];
        float hz = g_GH[r * 384 + 128 + h];
        float hn = g_GH[r * 384 + 256 + h];
        float rr = 1.f / (1.f + expf(-(ir + hr)));
        float zz = 1.f / (1.f + expf(-(iz + hz)));
        float nn = tanhf(in_ + rr * hn);
        g_newMem[idx] = (1.f - zz) * nn + zz * g_Hst[idx];
    } else if (b < 5346) {
        int j = (b - 4096) * 256 + tid;
        if (j < NE) {
            int d = ei[NE + j];
            int pos = atomicAdd(&g_cur[d], 1);
            g_ss[pos] = ei[j];
            g_su[pos] = g_slot[eids[j]];
        }
    } else {
        int t = (b - 5346) * 256 + tid;     // < 2*EVT
        if (t < 2 * EVT) {
            bool isD = t >= EVT;
            int i = isD ? t - EVT : t;
            int id = isD ? dids[i] : sids[i];
            int key = (isD ? DSTBIT : 0) | (i + 1);
            atomicMax(&g_tag[id], key);     // dst keys > src keys; monotone across replays
        }
    }
}

// ------------------- x = node_features + updated memory -------------------
__global__ void k_x(const int* __restrict__ node_ids,
                    const float* __restrict__ node_features,
                    const float* __restrict__ memory)
{
    int idx = blockIdx.x * blockDim.x + threadIdx.x;
    int r = idx >> 7, h = idx & 127;
    int gid = node_ids[r];
    int tg = g_tag[gid];
    float mv;
    if (tg == 0)             mv = memory[gid * H + h];
    else if (tg & DSTBIT)    mv = g_newMem[(EVT + (tg & ~DSTBIT) - 1) * H + h];
    else                     mv = g_newMem[(tg - 1) * H + h];
    g_x[idx] = node_features[gid * H + h] + mv;
}

// ------------------- fused attention: online softmax, one warp/node -------------------
__global__ void __launch_bounds__(256) k_attn(float* __restrict__ out) {
    int warp = threadIdx.x >> 5, lane = threadIdx.x & 31;
    int d = blockIdx.x * 8 + warp;
    if (d >= NN) return;
    int off0 = g_off[d], off1 = g_off[d + 1];

    float4 q4 = *(const float4*)&g_qkvs[(size_t)d * 512 + lane * 4];
    float m = -1e30f, den = 0.f;
    float4 acc = make_float4(0.f, 0.f, 0.f, 0.f);

    for (int i = off0; i < off1; i++) {
        int s = g_ss[i], u = g_su[i];
        float4 k4 = *(const float4*)&g_qkvs[(size_t)s * 512 + 128 + lane * 4];
        float4 e4 = *(const float4*)&g_Ec  [(size_t)u * H   +       lane * 4];
        float4 v4 = *(const float4*)&g_qkvs[(size_t)s * 512 + 256 + lane * 4];
        float p = q4.x * (k4.x + e4.x) + q4.y * (k4.y + e4.y)
                + q4.z * (k4.z + e4.z) + q4.w * (k4.w + e4.w);
#pragma unroll
        for (int o = 16; o; o >>= 1) p += __shfl_xor_sync(0xffffffffu, p, o);
        float a = p * 0.08838834764831845f;          // 1/sqrt(128)
        float mn = fmaxf(m, a);
        float scale = __expf(m - mn);                // first iter: exp(-inf)=0
        float w = __expf(a - mn);
        den = den * scale + w;
        acc.x = acc.x * scale + w * (v4.x + e4.x);
        acc.y = acc.y * scale + w * (v4.y + e4.y);
        acc.z = acc.z * scale + w * (v4.z + e4.z);
        acc.w = acc.w * scale + w * (v4.w + e4.w);
        m = mn;
    }
    float rden = 1.f / fmaxf(den, 1e-16f);
    float4 sk = *(const float4*)&g_qkvs[(size_t)d * 512 + 384 + lane * 4];
    float4 o4 = make_float4(sk.x + acc.x * rden, sk.y + acc.y * rden,
                            sk.z + acc.z * rden, sk.w + acc.w * rden);
    *(float4*)&out[(size_t)d * H + lane * 4] = o4;
}

// ------------------- reset flags/count (replay-idempotent) -------------------
__global__ void k_unflag(const int* __restrict__ eids) {
    int j = blockIdx.x * blockDim.x + threadIdx.x;
    if (j < NE) g_flag[eids[j]] = 0;
    if (j == 0) g_ucount = 0;
}

// ------------------- host -------------------
static float* symf(const void* s) {
    void* p = nullptr;
    cudaGetSymbolAddress(&p, s);
    return (float*)p;
}

extern "C" void kernel_launch(void* const* d_in, const int* in_sizes, int n_in,
                              void* d_out, int out_size)
{
    const int*   event_type_ids = (const int*)  d_in[0];
    const int*   src_ids        = (const int*)  d_in[1];
    const float* src_mask       = (const float*)d_in[2];
    const int*   dst_ids        = (const int*)  d_in[3];
    const float* dst_mask       = (const float*)d_in[4];
    const int*   event_edge_ids = (const int*)  d_in[5];
    const float* event_emb      = (const float*)d_in[6];
    const float* event_mask     = (const float*)d_in[7];
    const float* event_ts       = (const float*)d_in[8];
    const int*   node_ids       = (const int*)  d_in[9];
    const int*   edge_ids       = (const int*)  d_in[10];
    const int*   edge_index     = (const int*)  d_in[11];
    const void*  timep          =               d_in[12];
    const float* memory         = (const float*)d_in[13];
    const float* last_update    = (const float*)d_in[14];
    const float* node_features  = (const float*)d_in[15];
    const float* edge_features  = (const float*)d_in[16];
    const float* time_w         = (const float*)d_in[17];
    const float* time_b         = (const float*)d_in[18];
    const float* gru_w_ih       = (const float*)d_in[19];
    const float* gru_w_hh       = (const float*)d_in[20];
    const float* gru_b_ih       = (const float*)d_in[21];
    const float* gru_b_hh       = (const float*)d_in[22];
    const float* wq             = (const float*)d_in[23];
    const float* bq             = (const float*)d_in[24];
    const float* wk             = (const float*)d_in[25];
    const float* bk             = (const float*)d_in[26];
    const float* wv             = (const float*)d_in[27];
    const float* bv             = (const float*)d_in[28];
    const float* we             = (const float*)d_in[29];
    const float* wskip          = (const float*)d_in[30];
    const float* bskip          = (const float*)d_in[31];
    float* out = (float*)d_out;

    float* pEc   = symf(g_Ec);
    float* px    = symf(g_x);
    float* pqkvs = symf(g_qkvs);
    float* pweT  = symf(g_weT);
    float* pwc   = symf(g_wcT);
    float* pbc   = symf(g_bc);

    // K1: prep (transposes, packw, flag, cnt0, zero)
    k_prep<<<6961, 256>>>(gru_w_ih, gru_w_hh, we, wq, wk, wv, wskip,
                          bq, bk, bv, bskip, edge_ids, src_ids, dst_ids);
    // K2: msg + hist + urelt
    k_phase2<<<6892, 256>>>(event_type_ids, src_ids, src_mask, dst_ids, dst_mask,
                            event_edge_ids, event_emb, event_mask, event_ts,
                            last_update, memory, time_w, time_b, edge_index, timep);
    // K3: build_xh + scan
    k_phase3<<<2 * EVT + 1, 512>>>(src_ids, dst_ids, memory);
    // K4: GRU GEMMs (both in one launch)
    k_gru_gemms<<<dim3(64, 3, 2), 256>>>(gru_b_ih, gru_b_hh);
    // K5: fused E-GEMM over unique eids
    k_egemm<<<(MAXE + 127) / 128, 256>>>(edge_features, time_w, time_b, pweT, pEc);
    // K6: gru_act + scatter + tag
    k_phase4<<<5378, 256>>>(edge_index, edge_ids, src_ids, dst_ids);
    // K7: x = node_features + updated memory
    k_x<<<(NN * H) / 256, 256>>>(node_ids, node_features, memory);
    // K8: fused q|k|v|skip GEMM
    k_gemm_tc<<<dim3((NN + 127) / 128, 4), 256>>>(px, pwc, pbc, pqkvs, NN, 128, 512);
    // K9: fused flash-style attention + skip
    k_attn<<<(NN + 7) / 8, 256>>>(out);
    // K10: reset (replay-idempotent)
    k_unflag<<<(NE + 255) / 256, 256>>>(edge_ids);
}